// round 10
// baseline (speedup 1.0000x reference)
#include <cuda_runtime.h>
#include <cuda_bf16.h>
#include <mma.h>
#include <cstdint>

using namespace nvcuda;

#define NUSER 100000
#define NITEM 50000
#define NSEG  150000            // NUSER + NITEM
#define NEDGE 400000
#define DIN 128
#define BCAP 64                 // per-destination bucket capacity (max degree ~30)

// Scratch (allocation-free rule: __device__ globals)
__device__ float g_Qu[(size_t)NUSER * DIN];
__device__ float g_Ku[(size_t)NUSER * DIN];
__device__ float g_Vu[(size_t)NUSER * DIN];
__device__ float g_Qi[(size_t)NITEM * DIN];
__device__ float g_Ki[(size_t)NITEM * DIN];
__device__ float g_Vi[(size_t)NITEM * DIN];
__device__ int g_cnt[NSEG];
__device__ int g_srt[(size_t)NSEG * BCAP];
// pre-split weights: 6 matrices x {hi,lo} planes, logical [k][n] (n = h*32+e)
__device__ __nv_bfloat16 g_WB[6 * 2 * 128 * 128];

// ---------------- W pre-split: fp32 [h][k][e] -> bf16 hi/lo [k][n] ----------
__global__ __launch_bounds__(256) void split_w_kernel(
    const float* __restrict__ w0, const float* __restrict__ w1, const float* __restrict__ w2,
    const float* __restrict__ w3, const float* __restrict__ w4, const float* __restrict__ w5,
    __nv_bfloat16* __restrict__ WB)
{
    const int m = blockIdx.y;
    const float* w = m == 0 ? w0 : m == 1 ? w1 : m == 2 ? w2 : m == 3 ? w3 : m == 4 ? w4 : w5;
    __nv_bfloat16* hi = WB + (size_t)m * 2 * 16384;
    __nv_bfloat16* lo = hi + 16384;
    const int i = blockIdx.x * 256 + threadIdx.x;   // 64 blocks x 256 = 16384
    const int k = i >> 7, n = i & 127;
    const float v = w[(n >> 5) * 4096 + k * 32 + (n & 31)];
    const __nv_bfloat16 h = __float2bfloat16(v);
    hi[i] = h;
    lo[i] = __float2bfloat16(v - __bfloat162float(h));
}

// ============ projection GEMM (merged user+item) =============================
// Y[M,128] = X[M,128] @ Wlogical[128,128], bf16 wmma 3-term split emulation.
// blockIdx.x < tilesU -> user side; else item side. CTA stages its 64-row X
// tile once, loops over q/k/v weights. 8 loads / 12 mmas per k-step.
// ~102KB smem -> 2 CTAs/SM. Direct global epilogue (M % 16 == 0 holds).

static constexpr int LDA = 136;   // bf16 elems (272B rows)
static constexpr int LDB = 136;
static constexpr int SMEM_PROJ = (2 * 64 * LDA + 2 * 128 * LDB) * 2;  // 104448 B

__global__ __launch_bounds__(256, 2) void proj_wmma(
    const float* __restrict__ Xu, const float* __restrict__ Xi,
    const __nv_bfloat16* __restrict__ WB,
    float* __restrict__ Qu, float* __restrict__ Ku, float* __restrict__ Vu,
    float* __restrict__ Qi, float* __restrict__ Ki, float* __restrict__ Vi,
    int Mu, int Mi, int tilesU)
{
    extern __shared__ char smraw[];
    __nv_bfloat16* Ah = (__nv_bfloat16*)smraw;          // 64 x LDA
    __nv_bfloat16* Al = Ah + 64 * LDA;
    __nv_bfloat16* Bh = Al + 64 * LDA;                  // 128 x LDB
    __nv_bfloat16* Bl = Bh + 128 * LDB;

    const int tid  = threadIdx.x;
    const int wid  = tid >> 5;
    const int lane = tid & 31;

    const bool isU = (int)blockIdx.x < tilesU;
    const int tile0 = (isU ? blockIdx.x : blockIdx.x - tilesU) * 64;
    const int M = isU ? Mu : Mi;
    const float* X = isU ? Xu : Xi;
    const __nv_bfloat16* WBs = WB + (isU ? 0 : (size_t)3 * 2 * 16384);
    float* Ys[3] = { isU ? Qu : Qi, isU ? Ku : Ki, isU ? Vu : Vi };

    // ---- stage X tile ONCE -> Ah/Al (warp per row, float4 per lane) ----
    #pragma unroll
    for (int r0 = 0; r0 < 64; r0 += 8) {
        const int row = r0 + wid;
        const int grow = tile0 + row;
        float4 av = make_float4(0.f, 0.f, 0.f, 0.f);
        if (grow < M) av = *(const float4*)(X + (size_t)grow * 128 + lane * 4);
        const float vs[4] = {av.x, av.y, av.z, av.w};
        __nv_bfloat16 hb[4], lb[4];
        #pragma unroll
        for (int j = 0; j < 4; j++) {
            hb[j] = __float2bfloat16(vs[j]);
            lb[j] = __float2bfloat16(vs[j] - __bfloat162float(hb[j]));
        }
        *(uint2*)&Ah[row * LDA + lane * 4] = *(const uint2*)hb;
        *(uint2*)&Al[row * LDA + lane * 4] = *(const uint2*)lb;
    }

    const int wr = wid >> 2;          // warp row (32 rows)
    const int wc = wid & 3;           // warp col (32 cols)

    for (int mSel = 0; mSel < 3; mSel++) {
        __syncthreads();   // A visible (iter 0) / prev iter's B frag reads done

        // ---- stage B_mSel (both planes, uint4 copies) ----
        const __nv_bfloat16* Wm = WBs + (size_t)mSel * 2 * 16384;
        const uint4* srcH = (const uint4*)Wm;           // 2048 uint4 per plane
        const uint4* srcL = (const uint4*)(Wm + 16384);
        #pragma unroll
        for (int i = tid; i < 2048; i += 256) {
            const int k = i >> 4, n0 = (i & 15) * 8;
            *(uint4*)&Bh[k * LDB + n0] = srcH[i];
            *(uint4*)&Bl[k * LDB + n0] = srcL[i];
        }
        __syncthreads();

        // ---- compute: 8 fragment loads per k-step, 12 mmas ----
        wmma::fragment<wmma::accumulator, 16, 16, 16, float> c[2][2];
        #pragma unroll
        for (int i = 0; i < 2; i++)
            #pragma unroll
            for (int j = 0; j < 2; j++) wmma::fill_fragment(c[i][j], 0.f);

        #pragma unroll
        for (int k = 0; k < 128; k += 16) {
            wmma::fragment<wmma::matrix_a, 16, 16, 16, __nv_bfloat16, wmma::row_major> ah[2], al[2];
            wmma::fragment<wmma::matrix_b, 16, 16, 16, __nv_bfloat16, wmma::row_major> bh[2], bl[2];
            #pragma unroll
            for (int i = 0; i < 2; i++) {
                wmma::load_matrix_sync(ah[i], Ah + (wr * 32 + i * 16) * LDA + k, LDA);
                wmma::load_matrix_sync(al[i], Al + (wr * 32 + i * 16) * LDA + k, LDA);
            }
            #pragma unroll
            for (int j = 0; j < 2; j++) {
                wmma::load_matrix_sync(bh[j], Bh + k * LDB + wc * 32 + j * 16, LDB);
                wmma::load_matrix_sync(bl[j], Bl + k * LDB + wc * 32 + j * 16, LDB);
            }
            #pragma unroll
            for (int i = 0; i < 2; i++)
                #pragma unroll
                for (int j = 0; j < 2; j++) {
                    wmma::mma_sync(c[i][j], ah[i], bh[j], c[i][j]);
                    wmma::mma_sync(c[i][j], al[i], bh[j], c[i][j]);
                    wmma::mma_sync(c[i][j], ah[i], bl[j], c[i][j]);
                }
        }

        // ---- epilogue: direct global stores (M % 16 == 0) ----
        float* Y = Ys[mSel];
        #pragma unroll
        for (int i = 0; i < 2; i++) {
            const int grow = tile0 + wr * 32 + i * 16;
            if (grow + 16 <= M) {
                #pragma unroll
                for (int j = 0; j < 2; j++)
                    wmma::store_matrix_sync(Y + (size_t)grow * 128 + wc * 32 + j * 16,
                                            c[i][j], 128, wmma::mem_row_major);
            }
        }
    }
}

// ======= bucket scatter: single pass, atomic bump into fixed buckets ========
__global__ __launch_bounds__(256) void bucket_kernel(
    const int* __restrict__ eu, const int* __restrict__ ei,
    int* __restrict__ cnt, int* __restrict__ srt, int nE)
{
    const int t = blockIdx.x * 256 + threadIdx.x;
    if (t < nE) {
        const int d = eu[t];
        const int p = atomicAdd(&cnt[d], 1);
        if (p < BCAP) srt[(size_t)d * BCAP + p] = ei[t];
    } else if (t < 2 * nE) {
        const int e = t - nE;
        const int d = NUSER + ei[e];
        const int p = atomicAdd(&cnt[d], 1);
        if (p < BCAP) srt[(size_t)d * BCAP + p] = eu[e];
    }
}

// ============== gather: one warp per destination, fused finalize ============
// Indices staged warp-wide (1-2 coalesced loads, shfl-distributed). 2-edge
// batches, 4 edges in flight; __expf fast path. Writes relu(num/den) direct.
__global__ __launch_bounds__(256, 4) void gather_kernel(
    const float* __restrict__ Qu, const float* __restrict__ Ki, const float* __restrict__ Vi,
    const float* __restrict__ Qi, const float* __restrict__ Ku, const float* __restrict__ Vu,
    const int* __restrict__ cnt, const int* __restrict__ srt,
    float* __restrict__ out)
{
    const int g = blockIdx.x * 8 + (threadIdx.x >> 5);
    if (g >= NSEG) return;
    const int lane = threadIdx.x & 31;
    const int c4 = (lane & 7) * 4 + (lane >> 3) * 32;   // this lane's 4 dims

    float* zp = out + (size_t)g * 128 + c4;
    const int c = min(cnt[g], BCAP);
    if (c == 0) {
        *(float4*)zp = make_float4(0.f, 0.f, 0.f, 0.f);
        return;
    }

    const float *Q, *K, *V;
    int qrow;
    if (g < NUSER) { Q = Qu; K = Ki; V = Vi; qrow = g; }
    else           { Q = Qi; K = Ku; V = Vu; qrow = g - NUSER; }

    const int st = g * BCAP;
    // stage ALL bucket indices warp-wide (coalesced), distribute via shfl
    const int iA = __ldg(srt + st + min(lane, c - 1));
    const int iB = (c > 32) ? __ldg(srt + st + min(32 + lane, c - 1)) : 0;

    const float4 q4 = *(const float4*)(Q + (size_t)qrow * 128 + c4);

    #define IDXOF(j) ({ const int _jj = min((j), c - 1); \
        (_jj < 32) ? __shfl_sync(0xffffffffu, iA, _jj) \
                   : __shfl_sync(0xffffffffu, iB, _jj - 32); })

    // pipeline: batches of 2 edges, depth 2 (4 edges in flight)
    float4 k0, v0, k1, v1, nk0, nv0, nk1, nv1;
    {
        const int s0 = IDXOF(0), s1 = IDXOF(1);
        k0 = *(const float4*)(K + (size_t)s0 * 128 + c4);
        v0 = *(const float4*)(V + (size_t)s0 * 128 + c4);
        k1 = *(const float4*)(K + (size_t)s1 * 128 + c4);
        v1 = *(const float4*)(V + (size_t)s1 * 128 + c4);
        const int s2 = IDXOF(2), s3 = IDXOF(3);
        nk0 = *(const float4*)(K + (size_t)s2 * 128 + c4);
        nv0 = *(const float4*)(V + (size_t)s2 * 128 + c4);
        nk1 = *(const float4*)(K + (size_t)s3 * 128 + c4);
        nv1 = *(const float4*)(V + (size_t)s3 * 128 + c4);
    }

    float ax = 0.f, ay = 0.f, az = 0.f, aw = 0.f, den = 0.f;
    const int cPad = (c + 1) & ~1;
    for (int j = 0; j < cPad; j += 2) {
        const float4 ka = k0, va = v0, kb = k1, vb = v1;
        k0 = nk0; v0 = nv0; k1 = nk1; v1 = nv1;
        if (j + 4 < cPad) {
            const int s2 = IDXOF(j + 4), s3 = IDXOF(j + 5);
            nk0 = *(const float4*)(K + (size_t)s2 * 128 + c4);
            nv0 = *(const float4*)(V + (size_t)s2 * 128 + c4);
            nk1 = *(const float4*)(K + (size_t)s3 * 128 + c4);
            nv1 = *(const float4*)(V + (size_t)s3 * 128 + c4);
        }
        // two independent reduce/exp chains (interleaved by scheduler)
        float p0 = q4.x * ka.x + q4.y * ka.y + q4.z * ka.z + q4.w * ka.w;
        float p1 = q4.x * kb.x + q4.y * kb.y + q4.z * kb.z + q4.w * kb.w;
        p0 += __shfl_xor_sync(0xffffffffu, p0, 1);
        p1 += __shfl_xor_sync(0xffffffffu, p1, 1);
        p0 += __shfl_xor_sync(0xffffffffu, p0, 2);
        p1 += __shfl_xor_sync(0xffffffffu, p1, 2);
        p0 += __shfl_xor_sync(0xffffffffu, p0, 4);
        p1 += __shfl_xor_sync(0xffffffffu, p1, 4);
        const float w0 = __expf(p0);
        const float w1 = (j + 1 < c) ? __expf(p1) : 0.f;
        den += w0 + w1;
        ax += w0 * va.x + w1 * vb.x;
        ay += w0 * va.y + w1 * vb.y;
        az += w0 * va.z + w1 * vb.z;
        aw += w0 * va.w + w1 * vb.w;
    }
    #undef IDXOF

    const float inv = 1.f / den;
    *(float4*)zp = make_float4(fmaxf(ax * inv, 0.f), fmaxf(ay * inv, 0.f),
                               fmaxf(az * inv, 0.f), fmaxf(aw * inv, 0.f));
}

extern "C" void kernel_launch(void* const* d_in, const int* in_sizes, int n_in,
                              void* d_out, int out_size)
{
    const float* h_user    = (const float*)d_in[0];
    const float* h_item    = (const float*)d_in[1];
    const int*   edge_user = (const int*)d_in[2];
    const int*   edge_item = (const int*)d_in[3];
    const float* u_wq = (const float*)d_in[4];
    const float* u_wk = (const float*)d_in[5];
    const float* u_wv = (const float*)d_in[6];
    const float* i_wq = (const float*)d_in[7];
    const float* i_wk = (const float*)d_in[8];
    const float* i_wv = (const float*)d_in[9];
    float* out = (float*)d_out;

    const int nE = in_sizes[2];
    const int Mu = in_sizes[0] / DIN;
    const int Mi = in_sizes[1] / DIN;

    float *Qu, *Ku, *Vu, *Qi, *Ki, *Vi;
    int *cnt, *srt;
    __nv_bfloat16* WB;
    cudaGetSymbolAddress((void**)&Qu, g_Qu);
    cudaGetSymbolAddress((void**)&Ku, g_Ku);
    cudaGetSymbolAddress((void**)&Vu, g_Vu);
    cudaGetSymbolAddress((void**)&Qi, g_Qi);
    cudaGetSymbolAddress((void**)&Ki, g_Ki);
    cudaGetSymbolAddress((void**)&Vi, g_Vi);
    cudaGetSymbolAddress((void**)&cnt, g_cnt);
    cudaGetSymbolAddress((void**)&srt, g_srt);
    cudaGetSymbolAddress((void**)&WB, g_WB);

    cudaFuncSetAttribute(proj_wmma, cudaFuncAttributeMaxDynamicSharedMemorySize, SMEM_PROJ);

    // ---- bucket build ----
    cudaMemsetAsync(cnt, 0, sizeof(int) * NSEG);
    const int eb = (2 * nE + 255) / 256;
    bucket_kernel<<<eb, 256>>>(edge_user, edge_item, cnt, srt, nE);

    // ---- projections (one merged launch) ----
    split_w_kernel<<<dim3(64, 6), 256>>>(u_wq, u_wk, u_wv, i_wq, i_wk, i_wv, WB);
    const int tilesU = (Mu + 63) / 64, tilesI = (Mi + 63) / 64;
    proj_wmma<<<tilesU + tilesI, 256, SMEM_PROJ>>>(h_user, h_item, WB,
                                                   Qu, Ku, Vu, Qi, Ki, Vi, Mu, Mi, tilesU);

    // ---- fused attention gather + softmax-normalize + relu ----
    gather_kernel<<<(NSEG + 7) / 8, 256>>>(Qu, Ki, Vi, Qi, Ku, Vu, cnt, srt, out);
}

// round 11
// speedup vs baseline: 1.0241x; 1.0241x over previous
#include <cuda_runtime.h>
#include <cuda_bf16.h>
#include <mma.h>
#include <cstdint>

using namespace nvcuda;

#define NUSER 100000
#define NITEM 50000
#define NSEG  150000            // NUSER + NITEM
#define NEDGE 400000
#define DIN 128
#define BCAP 64                 // per-destination bucket capacity (max degree ~30)

// Scratch (allocation-free rule: __device__ globals)
__device__ float g_Qu[(size_t)NUSER * DIN];
__device__ float g_Ku[(size_t)NUSER * DIN];
__device__ float g_Vu[(size_t)NUSER * DIN];
__device__ float g_Qi[(size_t)NITEM * DIN];
__device__ float g_Ki[(size_t)NITEM * DIN];
__device__ float g_Vi[(size_t)NITEM * DIN];
__device__ int g_cnt[NSEG];
__device__ int g_srt[(size_t)NSEG * BCAP];
// pre-split weights: 6 matrices x {hi,lo} planes, logical [k][n] (n = h*32+e)
__device__ __nv_bfloat16 g_WB[6 * 2 * 128 * 128];

// ---------------- W pre-split: fp32 [h][k][e] -> bf16 hi/lo [k][n] ----------
__global__ __launch_bounds__(256) void split_w_kernel(
    const float* __restrict__ w0, const float* __restrict__ w1, const float* __restrict__ w2,
    const float* __restrict__ w3, const float* __restrict__ w4, const float* __restrict__ w5,
    __nv_bfloat16* __restrict__ WB)
{
    const int m = blockIdx.y;
    const float* w = m == 0 ? w0 : m == 1 ? w1 : m == 2 ? w2 : m == 3 ? w3 : m == 4 ? w4 : w5;
    __nv_bfloat16* hi = WB + (size_t)m * 2 * 16384;
    __nv_bfloat16* lo = hi + 16384;
    const int i = blockIdx.x * 256 + threadIdx.x;   // 64 blocks x 256 = 16384
    const int k = i >> 7, n = i & 127;
    const float v = w[(n >> 5) * 4096 + k * 32 + (n & 31)];
    const __nv_bfloat16 h = __float2bfloat16(v);
    hi[i] = h;
    lo[i] = __float2bfloat16(v - __bfloat162float(h));
}

// ============ projection GEMM (merged user+item) =============================
// Y[M,128] = X[M,128] @ Wlogical[128,128], bf16 wmma 3-term split emulation.
// blockIdx.x < tilesU -> user side; else item side. CTA stages its 64-row X
// tile once, loops over q/k/v weights. 8 loads / 12 mmas per k-step.
// ~102KB smem -> 2 CTAs/SM. Direct global epilogue (M % 16 == 0 holds).

static constexpr int LDA = 136;   // bf16 elems (272B rows)
static constexpr int LDB = 136;
static constexpr int SMEM_PROJ = (2 * 64 * LDA + 2 * 128 * LDB) * 2;  // 104448 B

__global__ __launch_bounds__(256, 2) void proj_wmma(
    const float* __restrict__ Xu, const float* __restrict__ Xi,
    const __nv_bfloat16* __restrict__ WB,
    float* __restrict__ Qu, float* __restrict__ Ku, float* __restrict__ Vu,
    float* __restrict__ Qi, float* __restrict__ Ki, float* __restrict__ Vi,
    int Mu, int Mi, int tilesU)
{
    extern __shared__ char smraw[];
    __nv_bfloat16* Ah = (__nv_bfloat16*)smraw;          // 64 x LDA
    __nv_bfloat16* Al = Ah + 64 * LDA;
    __nv_bfloat16* Bh = Al + 64 * LDA;                  // 128 x LDB
    __nv_bfloat16* Bl = Bh + 128 * LDB;

    const int tid  = threadIdx.x;
    const int wid  = tid >> 5;
    const int lane = tid & 31;

    const bool isU = (int)blockIdx.x < tilesU;
    const int tile0 = (isU ? blockIdx.x : blockIdx.x - tilesU) * 64;
    const int M = isU ? Mu : Mi;
    const float* X = isU ? Xu : Xi;
    const __nv_bfloat16* WBs = WB + (isU ? 0 : (size_t)3 * 2 * 16384);
    float* Ys[3] = { isU ? Qu : Qi, isU ? Ku : Ki, isU ? Vu : Vi };

    // ---- stage X tile ONCE -> Ah/Al (warp per row, float4 per lane) ----
    #pragma unroll
    for (int r0 = 0; r0 < 64; r0 += 8) {
        const int row = r0 + wid;
        const int grow = tile0 + row;
        float4 av = make_float4(0.f, 0.f, 0.f, 0.f);
        if (grow < M) av = *(const float4*)(X + (size_t)grow * 128 + lane * 4);
        const float vs[4] = {av.x, av.y, av.z, av.w};
        __nv_bfloat16 hb[4], lb[4];
        #pragma unroll
        for (int j = 0; j < 4; j++) {
            hb[j] = __float2bfloat16(vs[j]);
            lb[j] = __float2bfloat16(vs[j] - __bfloat162float(hb[j]));
        }
        *(uint2*)&Ah[row * LDA + lane * 4] = *(const uint2*)hb;
        *(uint2*)&Al[row * LDA + lane * 4] = *(const uint2*)lb;
    }

    const int wr = wid >> 2;          // warp row (32 rows)
    const int wc = wid & 3;           // warp col (32 cols)

    for (int mSel = 0; mSel < 3; mSel++) {
        __syncthreads();   // A visible (iter 0) / prev iter's B frag reads done

        // ---- stage B_mSel (both planes, uint4 copies) ----
        const __nv_bfloat16* Wm = WBs + (size_t)mSel * 2 * 16384;
        const uint4* srcH = (const uint4*)Wm;           // 2048 uint4 per plane
        const uint4* srcL = (const uint4*)(Wm + 16384);
        #pragma unroll
        for (int i = tid; i < 2048; i += 256) {
            const int k = i >> 4, n0 = (i & 15) * 8;
            *(uint4*)&Bh[k * LDB + n0] = srcH[i];
            *(uint4*)&Bl[k * LDB + n0] = srcL[i];
        }
        __syncthreads();

        // ---- compute: 8 fragment loads per k-step, 12 mmas ----
        wmma::fragment<wmma::accumulator, 16, 16, 16, float> c[2][2];
        #pragma unroll
        for (int i = 0; i < 2; i++)
            #pragma unroll
            for (int j = 0; j < 2; j++) wmma::fill_fragment(c[i][j], 0.f);

        #pragma unroll
        for (int k = 0; k < 128; k += 16) {
            wmma::fragment<wmma::matrix_a, 16, 16, 16, __nv_bfloat16, wmma::row_major> ah[2], al[2];
            wmma::fragment<wmma::matrix_b, 16, 16, 16, __nv_bfloat16, wmma::row_major> bh[2], bl[2];
            #pragma unroll
            for (int i = 0; i < 2; i++) {
                wmma::load_matrix_sync(ah[i], Ah + (wr * 32 + i * 16) * LDA + k, LDA);
                wmma::load_matrix_sync(al[i], Al + (wr * 32 + i * 16) * LDA + k, LDA);
            }
            #pragma unroll
            for (int j = 0; j < 2; j++) {
                wmma::load_matrix_sync(bh[j], Bh + k * LDB + wc * 32 + j * 16, LDB);
                wmma::load_matrix_sync(bl[j], Bl + k * LDB + wc * 32 + j * 16, LDB);
            }
            #pragma unroll
            for (int i = 0; i < 2; i++)
                #pragma unroll
                for (int j = 0; j < 2; j++) {
                    wmma::mma_sync(c[i][j], ah[i], bh[j], c[i][j]);
                    wmma::mma_sync(c[i][j], al[i], bh[j], c[i][j]);
                    wmma::mma_sync(c[i][j], ah[i], bl[j], c[i][j]);
                }
        }

        // ---- epilogue: direct global stores (M % 16 == 0) ----
        float* Y = Ys[mSel];
        #pragma unroll
        for (int i = 0; i < 2; i++) {
            const int grow = tile0 + wr * 32 + i * 16;
            if (grow + 16 <= M) {
                #pragma unroll
                for (int j = 0; j < 2; j++)
                    wmma::store_matrix_sync(Y + (size_t)grow * 128 + wc * 32 + j * 16,
                                            c[i][j], 128, wmma::mem_row_major);
            }
        }
    }
}

// ======= bucket scatter: single pass, atomic bump into fixed buckets ========
__global__ __launch_bounds__(256) void bucket_kernel(
    const int* __restrict__ eu, const int* __restrict__ ei,
    int* __restrict__ cnt, int* __restrict__ srt, int nE)
{
    const int t = blockIdx.x * 256 + threadIdx.x;
    if (t < nE) {
        const int d = eu[t];
        const int p = atomicAdd(&cnt[d], 1);
        if (p < BCAP) srt[(size_t)d * BCAP + p] = ei[t];
    } else if (t < 2 * nE) {
        const int e = t - nE;
        const int d = NUSER + ei[e];
        const int p = atomicAdd(&cnt[d], 1);
        if (p < BCAP) srt[(size_t)d * BCAP + p] = eu[e];
    }
}

// ============== gather: one warp per destination, fused finalize ============
// lane l: head h = l>>3, dims (l&7)*4. Q in registers; depth-2 software
// pipeline on edge K/V gathers; __expf fast path; writes relu(num/den).
__global__ __launch_bounds__(256, 4) void gather_kernel(
    const float* __restrict__ Qu, const float* __restrict__ Ki, const float* __restrict__ Vi,
    const float* __restrict__ Qi, const float* __restrict__ Ku, const float* __restrict__ Vu,
    const int* __restrict__ cnt, const int* __restrict__ srt,
    float* __restrict__ out)
{
    const int g = blockIdx.x * 8 + (threadIdx.x >> 5);
    if (g >= NSEG) return;
    const int lane = threadIdx.x & 31;
    const int c4 = (lane & 7) * 4 + (lane >> 3) * 32;   // this lane's 4 dims

    float* zp = out + (size_t)g * 128 + c4;
    const int c = min(cnt[g], BCAP);
    if (c == 0) {
        *(float4*)zp = make_float4(0.f, 0.f, 0.f, 0.f);
        return;
    }

    const float *Q, *K, *V;
    int qrow;
    if (g < NUSER) { Q = Qu; K = Ki; V = Vi; qrow = g; }
    else           { Q = Qi; K = Ku; V = Vu; qrow = g - NUSER; }

    const float4 q4 = *(const float4*)(Q + (size_t)qrow * 128 + c4);
    const int st = g * BCAP;

    // depth-2 prefetch pipeline
    float4 k0, v0, k1, v1;
    {
        const int s0 = __ldg(srt + st);
        k0 = *(const float4*)(K + (size_t)s0 * 128 + c4);
        v0 = *(const float4*)(V + (size_t)s0 * 128 + c4);
    }
    if (c > 1) {
        const int s1 = __ldg(srt + st + 1);
        k1 = *(const float4*)(K + (size_t)s1 * 128 + c4);
        v1 = *(const float4*)(V + (size_t)s1 * 128 + c4);
    }

    float ax = 0.f, ay = 0.f, az = 0.f, aw = 0.f, den = 0.f;
    for (int j = 0; j < c; j++) {
        const float4 k4 = k0, v4 = v0;
        k0 = k1; v0 = v1;
        if (j + 2 < c) {
            const int sn = __ldg(srt + st + j + 2);
            k1 = *(const float4*)(K + (size_t)sn * 128 + c4);
            v1 = *(const float4*)(V + (size_t)sn * 128 + c4);
        }
        float p = q4.x * k4.x + q4.y * k4.y + q4.z * k4.z + q4.w * k4.w;
        p += __shfl_xor_sync(0xffffffffu, p, 1);
        p += __shfl_xor_sync(0xffffffffu, p, 2);
        p += __shfl_xor_sync(0xffffffffu, p, 4);
        const float w = __expf(p);
        den += w;
        ax += w * v4.x; ay += w * v4.y; az += w * v4.z; aw += w * v4.w;
    }
    const float inv = 1.f / den;
    *(float4*)zp = make_float4(fmaxf(ax * inv, 0.f), fmaxf(ay * inv, 0.f),
                               fmaxf(az * inv, 0.f), fmaxf(aw * inv, 0.f));
}

extern "C" void kernel_launch(void* const* d_in, const int* in_sizes, int n_in,
                              void* d_out, int out_size)
{
    const float* h_user    = (const float*)d_in[0];
    const float* h_item    = (const float*)d_in[1];
    const int*   edge_user = (const int*)d_in[2];
    const int*   edge_item = (const int*)d_in[3];
    const float* u_wq = (const float*)d_in[4];
    const float* u_wk = (const float*)d_in[5];
    const float* u_wv = (const float*)d_in[6];
    const float* i_wq = (const float*)d_in[7];
    const float* i_wk = (const float*)d_in[8];
    const float* i_wv = (const float*)d_in[9];
    float* out = (float*)d_out;

    const int nE = in_sizes[2];
    const int Mu = in_sizes[0] / DIN;
    const int Mi = in_sizes[1] / DIN;

    float *Qu, *Ku, *Vu, *Qi, *Ki, *Vi;
    int *cnt, *srt;
    __nv_bfloat16* WB;
    cudaGetSymbolAddress((void**)&Qu, g_Qu);
    cudaGetSymbolAddress((void**)&Ku, g_Ku);
    cudaGetSymbolAddress((void**)&Vu, g_Vu);
    cudaGetSymbolAddress((void**)&Qi, g_Qi);
    cudaGetSymbolAddress((void**)&Ki, g_Ki);
    cudaGetSymbolAddress((void**)&Vi, g_Vi);
    cudaGetSymbolAddress((void**)&cnt, g_cnt);
    cudaGetSymbolAddress((void**)&srt, g_srt);
    cudaGetSymbolAddress((void**)&WB, g_WB);

    cudaFuncSetAttribute(proj_wmma, cudaFuncAttributeMaxDynamicSharedMemorySize, SMEM_PROJ);

    // ---- bucket build ----
    cudaMemsetAsync(cnt, 0, sizeof(int) * NSEG);
    const int eb = (2 * nE + 255) / 256;
    bucket_kernel<<<eb, 256>>>(edge_user, edge_item, cnt, srt, nE);

    // ---- projections (one merged launch) ----
    split_w_kernel<<<dim3(64, 6), 256>>>(u_wq, u_wk, u_wv, i_wq, i_wk, i_wv, WB);
    const int tilesU = (Mu + 63) / 64, tilesI = (Mi + 63) / 64;
    proj_wmma<<<tilesU + tilesI, 256, SMEM_PROJ>>>(h_user, h_item, WB,
                                                   Qu, Ku, Vu, Qi, Ki, Vi, Mu, Mi, tilesU);

    // ---- fused attention gather + softmax-normalize + relu ----
    gather_kernel<<<(NSEG + 7) / 8, 256>>>(Qu, Ki, Vi, Qi, Ku, Vu, cnt, srt, out);
}

// round 12
// speedup vs baseline: 1.0354x; 1.0110x over previous
#include <cuda_runtime.h>
#include <cuda_bf16.h>
#include <mma.h>
#include <cstdint>

using namespace nvcuda;

#define NUSER 100000
#define NITEM 50000
#define NSEG  150000            // NUSER + NITEM
#define NEDGE 400000
#define DIN 128
#define BCAP 64                 // per-destination bucket capacity (max degree ~30)

// Scratch (allocation-free rule: __device__ globals)
// Q separate [node][128]; K,V interleaved per node: [node][0:128)=K, [128:256)=V
__device__ float g_Qu[(size_t)NUSER * DIN];
__device__ float g_Qi[(size_t)NITEM * DIN];
__device__ float g_KVu[(size_t)NUSER * 256];
__device__ float g_KVi[(size_t)NITEM * 256];
__device__ int g_cnt[NSEG];
__device__ int g_srt[(size_t)NSEG * BCAP];
// pre-split weights: 6 matrices x {hi,lo} planes, logical [k][n] (n = h*32+e)
__device__ __nv_bfloat16 g_WB[6 * 2 * 128 * 128];

// ---------------- W pre-split: fp32 [h][k][e] -> bf16 hi/lo [k][n] ----------
__global__ __launch_bounds__(256) void split_w_kernel(
    const float* __restrict__ w0, const float* __restrict__ w1, const float* __restrict__ w2,
    const float* __restrict__ w3, const float* __restrict__ w4, const float* __restrict__ w5,
    __nv_bfloat16* __restrict__ WB)
{
    const int m = blockIdx.y;
    const float* w = m == 0 ? w0 : m == 1 ? w1 : m == 2 ? w2 : m == 3 ? w3 : m == 4 ? w4 : w5;
    __nv_bfloat16* hi = WB + (size_t)m * 2 * 16384;
    __nv_bfloat16* lo = hi + 16384;
    const int i = blockIdx.x * 256 + threadIdx.x;   // 64 blocks x 256 = 16384
    const int k = i >> 7, n = i & 127;
    const float v = w[(n >> 5) * 4096 + k * 32 + (n & 31)];
    const __nv_bfloat16 h = __float2bfloat16(v);
    hi[i] = h;
    lo[i] = __float2bfloat16(v - __bfloat162float(h));
}

// ============ projection GEMM (merged user+item) =============================
// Y[M,128] = X[M,128] @ Wlogical[128,128], bf16 wmma 3-term split emulation.
// blockIdx.x < tilesU -> user side; else item side. CTA stages its 64-row X
// tile once, loops over q/k/v weights. 8 loads / 12 mmas per k-step.
// Q stored at stride 128; K/V stored interleaved at stride 256 (K off 0,
// V off 128) so the gather reads one contiguous 1KB record per edge.
// ~102KB smem -> 2 CTAs/SM. Direct global epilogue (M % 16 == 0 holds).

static constexpr int LDA = 136;   // bf16 elems (272B rows)
static constexpr int LDB = 136;
static constexpr int SMEM_PROJ = (2 * 64 * LDA + 2 * 128 * LDB) * 2;  // 104448 B

__global__ __launch_bounds__(256, 2) void proj_wmma(
    const float* __restrict__ Xu, const float* __restrict__ Xi,
    const __nv_bfloat16* __restrict__ WB,
    float* __restrict__ Qu, float* __restrict__ Qi,
    float* __restrict__ KVu, float* __restrict__ KVi,
    int Mu, int Mi, int tilesU)
{
    extern __shared__ char smraw[];
    __nv_bfloat16* Ah = (__nv_bfloat16*)smraw;          // 64 x LDA
    __nv_bfloat16* Al = Ah + 64 * LDA;
    __nv_bfloat16* Bh = Al + 64 * LDA;                  // 128 x LDB
    __nv_bfloat16* Bl = Bh + 128 * LDB;

    const int tid  = threadIdx.x;
    const int wid  = tid >> 5;
    const int lane = tid & 31;

    const bool isU = (int)blockIdx.x < tilesU;
    const int tile0 = (isU ? blockIdx.x : blockIdx.x - tilesU) * 64;
    const int M = isU ? Mu : Mi;
    const float* X = isU ? Xu : Xi;
    const __nv_bfloat16* WBs = WB + (isU ? 0 : (size_t)3 * 2 * 16384);
    float* Qp  = isU ? Qu  : Qi;
    float* KVp = isU ? KVu : KVi;

    // ---- stage X tile ONCE -> Ah/Al (warp per row, float4 per lane) ----
    #pragma unroll
    for (int r0 = 0; r0 < 64; r0 += 8) {
        const int row = r0 + wid;
        const int grow = tile0 + row;
        float4 av = make_float4(0.f, 0.f, 0.f, 0.f);
        if (grow < M) av = *(const float4*)(X + (size_t)grow * 128 + lane * 4);
        const float vs[4] = {av.x, av.y, av.z, av.w};
        __nv_bfloat16 hb[4], lb[4];
        #pragma unroll
        for (int j = 0; j < 4; j++) {
            hb[j] = __float2bfloat16(vs[j]);
            lb[j] = __float2bfloat16(vs[j] - __bfloat162float(hb[j]));
        }
        *(uint2*)&Ah[row * LDA + lane * 4] = *(const uint2*)hb;
        *(uint2*)&Al[row * LDA + lane * 4] = *(const uint2*)lb;
    }

    const int wr = wid >> 2;          // warp row (32 rows)
    const int wc = wid & 3;           // warp col (32 cols)

    for (int mSel = 0; mSel < 3; mSel++) {
        __syncthreads();   // A visible (iter 0) / prev iter's B frag reads done

        // ---- stage B_mSel (both planes, uint4 copies) ----
        const __nv_bfloat16* Wm = WBs + (size_t)mSel * 2 * 16384;
        const uint4* srcH = (const uint4*)Wm;           // 2048 uint4 per plane
        const uint4* srcL = (const uint4*)(Wm + 16384);
        #pragma unroll
        for (int i = tid; i < 2048; i += 256) {
            const int k = i >> 4, n0 = (i & 15) * 8;
            *(uint4*)&Bh[k * LDB + n0] = srcH[i];
            *(uint4*)&Bl[k * LDB + n0] = srcL[i];
        }
        __syncthreads();

        // ---- compute: 8 fragment loads per k-step, 12 mmas ----
        wmma::fragment<wmma::accumulator, 16, 16, 16, float> c[2][2];
        #pragma unroll
        for (int i = 0; i < 2; i++)
            #pragma unroll
            for (int j = 0; j < 2; j++) wmma::fill_fragment(c[i][j], 0.f);

        #pragma unroll
        for (int k = 0; k < 128; k += 16) {
            wmma::fragment<wmma::matrix_a, 16, 16, 16, __nv_bfloat16, wmma::row_major> ah[2], al[2];
            wmma::fragment<wmma::matrix_b, 16, 16, 16, __nv_bfloat16, wmma::row_major> bh[2], bl[2];
            #pragma unroll
            for (int i = 0; i < 2; i++) {
                wmma::load_matrix_sync(ah[i], Ah + (wr * 32 + i * 16) * LDA + k, LDA);
                wmma::load_matrix_sync(al[i], Al + (wr * 32 + i * 16) * LDA + k, LDA);
            }
            #pragma unroll
            for (int j = 0; j < 2; j++) {
                wmma::load_matrix_sync(bh[j], Bh + k * LDB + wc * 32 + j * 16, LDB);
                wmma::load_matrix_sync(bl[j], Bl + k * LDB + wc * 32 + j * 16, LDB);
            }
            #pragma unroll
            for (int i = 0; i < 2; i++)
                #pragma unroll
                for (int j = 0; j < 2; j++) {
                    wmma::mma_sync(c[i][j], ah[i], bh[j], c[i][j]);
                    wmma::mma_sync(c[i][j], al[i], bh[j], c[i][j]);
                    wmma::mma_sync(c[i][j], ah[i], bl[j], c[i][j]);
                }
        }

        // ---- epilogue: direct global stores (M % 16 == 0) ----
        float* Y = (mSel == 0) ? Qp : KVp;
        const int ldY  = (mSel == 0) ? 128 : 256;
        const int coff = (mSel == 2) ? 128 : 0;
        #pragma unroll
        for (int i = 0; i < 2; i++) {
            const int grow = tile0 + wr * 32 + i * 16;
            if (grow + 16 <= M) {
                #pragma unroll
                for (int j = 0; j < 2; j++)
                    wmma::store_matrix_sync(Y + (size_t)grow * ldY + coff + wc * 32 + j * 16,
                                            c[i][j], ldY, wmma::mem_row_major);
            }
        }
    }
}

// ======= bucket scatter: single pass, atomic bump into fixed buckets ========
__global__ __launch_bounds__(256) void bucket_kernel(
    const int* __restrict__ eu, const int* __restrict__ ei,
    int* __restrict__ cnt, int* __restrict__ srt, int nE)
{
    const int t = blockIdx.x * 256 + threadIdx.x;
    if (t < nE) {
        const int d = eu[t];
        const int p = atomicAdd(&cnt[d], 1);
        if (p < BCAP) srt[(size_t)d * BCAP + p] = ei[t];
    } else if (t < 2 * nE) {
        const int e = t - nE;
        const int d = NUSER + ei[e];
        const int p = atomicAdd(&cnt[d], 1);
        if (p < BCAP) srt[(size_t)d * BCAP + p] = eu[e];
    }
}

// ============== gather: one warp per destination, fused finalize ============
// lane l: head h = l>>3, dims (l&7)*4. Q in registers; depth-2 software
// pipeline over contiguous 1KB KV records; __expf; writes relu(num/den).
__global__ __launch_bounds__(256, 4) void gather_kernel(
    const float* __restrict__ Qu, const float* __restrict__ Qi,
    const float* __restrict__ KVu, const float* __restrict__ KVi,
    const int* __restrict__ cnt, const int* __restrict__ srt,
    float* __restrict__ out)
{
    const int g = blockIdx.x * 8 + (threadIdx.x >> 5);
    if (g >= NSEG) return;
    const int lane = threadIdx.x & 31;
    const int c4 = (lane & 7) * 4 + (lane >> 3) * 32;   // this lane's 4 dims

    float* zp = out + (size_t)g * 128 + c4;
    const int c = min(cnt[g], BCAP);
    if (c == 0) {
        *(float4*)zp = make_float4(0.f, 0.f, 0.f, 0.f);
        return;
    }

    // dst side g: users attend over item KV; items over user KV
    const float* Q;
    const float* KV;
    int qrow;
    if (g < NUSER) { Q = Qu; KV = KVi; qrow = g; }
    else           { Q = Qi; KV = KVu; qrow = g - NUSER; }

    const float4 q4 = *(const float4*)(Q + (size_t)qrow * 128 + c4);
    const int st = g * BCAP;

    // depth-2 prefetch pipeline over 1KB KV records
    float4 k0, v0, k1, v1;
    {
        const float* r0 = KV + (size_t)__ldg(srt + st) * 256;
        k0 = *(const float4*)(r0 + c4);
        v0 = *(const float4*)(r0 + 128 + c4);
    }
    if (c > 1) {
        const float* r1 = KV + (size_t)__ldg(srt + st + 1) * 256;
        k1 = *(const float4*)(r1 + c4);
        v1 = *(const float4*)(r1 + 128 + c4);
    }

    float ax = 0.f, ay = 0.f, az = 0.f, aw = 0.f, den = 0.f;
    for (int j = 0; j < c; j++) {
        const float4 k4 = k0, v4 = v0;
        k0 = k1; v0 = v1;
        if (j + 2 < c) {
            const float* rn = KV + (size_t)__ldg(srt + st + j + 2) * 256;
            k1 = *(const float4*)(rn + c4);
            v1 = *(const float4*)(rn + 128 + c4);
        }
        float p = q4.x * k4.x + q4.y * k4.y + q4.z * k4.z + q4.w * k4.w;
        p += __shfl_xor_sync(0xffffffffu, p, 1);
        p += __shfl_xor_sync(0xffffffffu, p, 2);
        p += __shfl_xor_sync(0xffffffffu, p, 4);
        const float w = __expf(p);
        den += w;
        ax += w * v4.x; ay += w * v4.y; az += w * v4.z; aw += w * v4.w;
    }
    const float inv = 1.f / den;
    *(float4*)zp = make_float4(fmaxf(ax * inv, 0.f), fmaxf(ay * inv, 0.f),
                               fmaxf(az * inv, 0.f), fmaxf(aw * inv, 0.f));
}

extern "C" void kernel_launch(void* const* d_in, const int* in_sizes, int n_in,
                              void* d_out, int out_size)
{
    const float* h_user    = (const float*)d_in[0];
    const float* h_item    = (const float*)d_in[1];
    const int*   edge_user = (const int*)d_in[2];
    const int*   edge_item = (const int*)d_in[3];
    const float* u_wq = (const float*)d_in[4];
    const float* u_wk = (const float*)d_in[5];
    const float* u_wv = (const float*)d_in[6];
    const float* i_wq = (const float*)d_in[7];
    const float* i_wk = (const float*)d_in[8];
    const float* i_wv = (const float*)d_in[9];
    float* out = (float*)d_out;

    const int nE = in_sizes[2];
    const int Mu = in_sizes[0] / DIN;
    const int Mi = in_sizes[1] / DIN;

    float *Qu, *Qi, *KVu, *KVi;
    int *cnt, *srt;
    __nv_bfloat16* WB;
    cudaGetSymbolAddress((void**)&Qu, g_Qu);
    cudaGetSymbolAddress((void**)&Qi, g_Qi);
    cudaGetSymbolAddress((void**)&KVu, g_KVu);
    cudaGetSymbolAddress((void**)&KVi, g_KVi);
    cudaGetSymbolAddress((void**)&cnt, g_cnt);
    cudaGetSymbolAddress((void**)&srt, g_srt);
    cudaGetSymbolAddress((void**)&WB, g_WB);

    cudaFuncSetAttribute(proj_wmma, cudaFuncAttributeMaxDynamicSharedMemorySize, SMEM_PROJ);

    // ---- bucket build ----
    cudaMemsetAsync(cnt, 0, sizeof(int) * NSEG);
    const int eb = (2 * nE + 255) / 256;
    bucket_kernel<<<eb, 256>>>(edge_user, edge_item, cnt, srt, nE);

    // ---- projections (one merged launch) ----
    split_w_kernel<<<dim3(64, 6), 256>>>(u_wq, u_wk, u_wv, i_wq, i_wk, i_wv, WB);
    const int tilesU = (Mu + 63) / 64, tilesI = (Mi + 63) / 64;
    proj_wmma<<<tilesU + tilesI, 256, SMEM_PROJ>>>(h_user, h_item, WB,
                                                   Qu, Qi, KVu, KVi, Mu, Mi, tilesU);

    // ---- fused attention gather + softmax-normalize + relu ----
    gather_kernel<<<(NSEG + 7) / 8, 256>>>(Qu, Qi, KVu, KVi, cnt, srt, out);
}

// round 13
// speedup vs baseline: 1.0989x; 1.0613x over previous
#include <cuda_runtime.h>
#include <cuda_bf16.h>
#include <mma.h>
#include <cstdint>

using namespace nvcuda;

#define NUSER 100000
#define NITEM 50000
#define NSEG  150000            // NUSER + NITEM
#define NEDGE 400000
#define DIN 128
#define BCAP 64                 // per-destination bucket capacity (max degree ~30)

// Scratch (allocation-free rule: __device__ globals)
// Q separate [node][128]; K,V interleaved per node: [node][0:128)=K, [128:256)=V
__device__ float g_Qu[(size_t)NUSER * DIN];
__device__ float g_Qi[(size_t)NITEM * DIN];
__device__ float g_KVu[(size_t)NUSER * 256];
__device__ float g_KVi[(size_t)NITEM * 256];
__device__ int g_cnt[NSEG];
__device__ int g_srt[(size_t)NSEG * BCAP];
// pre-split weights: 6 matrices x {hi,lo} planes, logical [k][n] (n = h*32+e)
__device__ __nv_bfloat16 g_WB[6 * 2 * 128 * 128];

// ---------------- cp.async helpers (baseline sm_80 PTX) ---------------------
__device__ __forceinline__ void cp_async16(void* smem_dst, const void* gsrc) {
    const uint32_t s = (uint32_t)__cvta_generic_to_shared(smem_dst);
    asm volatile("cp.async.cg.shared.global [%0], [%1], 16;" :: "r"(s), "l"(gsrc));
}
#define CP_COMMIT() asm volatile("cp.async.commit_group;" ::: "memory")
#define CP_WAIT0()  asm volatile("cp.async.wait_group 0;" ::: "memory")

// ============ merged utility kernel: split_w (blocks 0..383) + bucket =======
// split_w: fp32 [h][k][e] -> bf16 hi/lo [k][n];  bucket: atomic-bump scatter.
__global__ __launch_bounds__(256) void util_kernel(
    const float* __restrict__ w0, const float* __restrict__ w1, const float* __restrict__ w2,
    const float* __restrict__ w3, const float* __restrict__ w4, const float* __restrict__ w5,
    __nv_bfloat16* __restrict__ WB,
    const int* __restrict__ eu, const int* __restrict__ ei,
    int* __restrict__ cnt, int* __restrict__ srt, int nE)
{
    const int bx = blockIdx.x;
    if (bx < 384) {              // ---- split_w part: 384 blocks x 256 = 6*16384
        const int m = bx >> 6;
        const float* w = m == 0 ? w0 : m == 1 ? w1 : m == 2 ? w2 : m == 3 ? w3 : m == 4 ? w4 : w5;
        __nv_bfloat16* hi = WB + (size_t)m * 2 * 16384;
        __nv_bfloat16* lo = hi + 16384;
        const int i = (bx & 63) * 256 + threadIdx.x;
        const int k = i >> 7, n = i & 127;
        const float v = w[(n >> 5) * 4096 + k * 32 + (n & 31)];
        const __nv_bfloat16 h = __float2bfloat16(v);
        hi[i] = h;
        lo[i] = __float2bfloat16(v - __bfloat162float(h));
    } else {                     // ---- bucket part
        const int t = (bx - 384) * 256 + threadIdx.x;
        if (t < nE) {
            const int d = eu[t];
            const int p = atomicAdd(&cnt[d], 1);
            if (p < BCAP) srt[(size_t)d * BCAP + p] = ei[t];
        } else if (t < 2 * nE) {
            const int e = t - nE;
            const int d = NUSER + ei[e];
            const int p = atomicAdd(&cnt[d], 1);
            if (p < BCAP) srt[(size_t)d * BCAP + p] = eu[e];
        }
    }
}

// ============ projection GEMM (merged user+item) =============================
// Y[M,128] = X[M,128] @ Wlogical[128,128], bf16 wmma 3-term split emulation.
// B staged in 64-k-row chunks (hi+lo, 32KB) via cp.async double buffering:
// chunk p+1 streams while MMAs run on chunk p; first chunk streams under the
// X-tile staging. 6 phases = 3 matrices x 2 chunks. smem same 102KB ->
// 2 CTAs/SM. Q stride 128; K/V interleaved stride 256. M % 16 == 0 holds.

static constexpr int LDA = 136;   // bf16 elems (272B rows)
static constexpr int LDB = 136;
static constexpr int A_BYTES   = 2 * 64 * LDA * 2;     // 34816
static constexpr int BBUF_BYTES = 2 * 64 * LDB * 2;    // 34816 (hi 64 rows + lo 64 rows)
static constexpr int SMEM_PROJ = A_BYTES + 2 * BBUF_BYTES;  // 104448 B

// stream one B chunk (phase = mSel*2 + c) into bufBase via cp.async
__device__ __forceinline__ void issue_b_chunk(
    const __nv_bfloat16* WBs, int phase, char* bufBase, int tid)
{
    const int mSel = phase >> 1, c = phase & 1;
    const __nv_bfloat16* Wm = WBs + (size_t)mSel * 2 * 16384;
    const char* srcHi = (const char*)(Wm + c * 8192);            // 16KB contiguous
    const char* srcLo = (const char*)(Wm + 16384 + c * 8192);
    #pragma unroll
    for (int i = tid; i < 2048; i += 256) {
        const int plane = i >> 10;            // 0 = hi, 1 = lo
        const int idx = i & 1023;             // uint4 index within plane chunk
        const int r = idx >> 4, c16 = idx & 15;   // 64 rows x 16 uint4/row
        char* dst = bufBase + plane * (64 * LDB * 2) + r * (LDB * 2) + c16 * 16;
        const char* s = (plane ? srcLo : srcHi) + (size_t)idx * 16;
        cp_async16(dst, s);
    }
}

__global__ __launch_bounds__(256, 2) void proj_wmma(
    const float* __restrict__ Xu, const float* __restrict__ Xi,
    const __nv_bfloat16* __restrict__ WB,
    float* __restrict__ Qu, float* __restrict__ Qi,
    float* __restrict__ KVu, float* __restrict__ KVi,
    int Mu, int Mi, int tilesU)
{
    extern __shared__ char smraw[];
    __nv_bfloat16* Ah = (__nv_bfloat16*)smraw;          // 64 x LDA
    __nv_bfloat16* Al = Ah + 64 * LDA;
    char* bBuf[2] = { smraw + A_BYTES, smraw + A_BYTES + BBUF_BYTES };

    const int tid  = threadIdx.x;
    const int wid  = tid >> 5;
    const int lane = tid & 31;

    const bool isU = (int)blockIdx.x < tilesU;
    const int tile0 = (isU ? blockIdx.x : blockIdx.x - tilesU) * 64;
    const int M = isU ? Mu : Mi;
    const float* X = isU ? Xu : Xi;
    const __nv_bfloat16* WBs = WB + (isU ? 0 : (size_t)3 * 2 * 16384);
    float* Qp  = isU ? Qu  : Qi;
    float* KVp = isU ? KVu : KVi;

    // ---- kick off B chunk 0 immediately (overlaps X staging) ----
    issue_b_chunk(WBs, 0, bBuf[0], tid);
    CP_COMMIT();

    // ---- stage X tile ONCE -> Ah/Al (warp per row, float4 per lane) ----
    #pragma unroll
    for (int r0 = 0; r0 < 64; r0 += 8) {
        const int row = r0 + wid;
        const int grow = tile0 + row;
        float4 av = make_float4(0.f, 0.f, 0.f, 0.f);
        if (grow < M) av = *(const float4*)(X + (size_t)grow * 128 + lane * 4);
        const float vs[4] = {av.x, av.y, av.z, av.w};
        __nv_bfloat16 hb[4], lb[4];
        #pragma unroll
        for (int j = 0; j < 4; j++) {
            hb[j] = __float2bfloat16(vs[j]);
            lb[j] = __float2bfloat16(vs[j] - __bfloat162float(hb[j]));
        }
        *(uint2*)&Ah[row * LDA + lane * 4] = *(const uint2*)hb;
        *(uint2*)&Al[row * LDA + lane * 4] = *(const uint2*)lb;
    }

    const int wr = wid >> 2;          // warp row (32 rows)
    const int wc = wid & 3;           // warp col (32 cols)
    int pb = 0;                        // current B buffer

    for (int mSel = 0; mSel < 3; mSel++) {
        wmma::fragment<wmma::accumulator, 16, 16, 16, float> c[2][2];
        #pragma unroll
        for (int i = 0; i < 2; i++)
            #pragma unroll
            for (int j = 0; j < 2; j++) wmma::fill_fragment(c[i][j], 0.f);

        #pragma unroll
        for (int ch = 0; ch < 2; ch++) {
            const int phase = mSel * 2 + ch;
            CP_WAIT0();          // our chunk `phase` is in
            __syncthreads();     // all threads' chunk in; all done reading the other buf
            if (phase + 1 < 6) {
                issue_b_chunk(WBs, phase + 1, bBuf[pb ^ 1], tid);
                CP_COMMIT();
            }
            const __nv_bfloat16* BhB = (const __nv_bfloat16*)bBuf[pb];
            const __nv_bfloat16* BlB = BhB + 64 * LDB;
            const int kBase = ch * 64;

            #pragma unroll
            for (int kk = 0; kk < 64; kk += 16) {
                wmma::fragment<wmma::matrix_a, 16, 16, 16, __nv_bfloat16, wmma::row_major> ah[2], al[2];
                wmma::fragment<wmma::matrix_b, 16, 16, 16, __nv_bfloat16, wmma::row_major> bh[2], bl[2];
                #pragma unroll
                for (int i = 0; i < 2; i++) {
                    wmma::load_matrix_sync(ah[i], Ah + (wr * 32 + i * 16) * LDA + kBase + kk, LDA);
                    wmma::load_matrix_sync(al[i], Al + (wr * 32 + i * 16) * LDA + kBase + kk, LDA);
                }
                #pragma unroll
                for (int j = 0; j < 2; j++) {
                    wmma::load_matrix_sync(bh[j], BhB + kk * LDB + wc * 32 + j * 16, LDB);
                    wmma::load_matrix_sync(bl[j], BlB + kk * LDB + wc * 32 + j * 16, LDB);
                }
                #pragma unroll
                for (int i = 0; i < 2; i++)
                    #pragma unroll
                    for (int j = 0; j < 2; j++) {
                        wmma::mma_sync(c[i][j], ah[i], bh[j], c[i][j]);
                        wmma::mma_sync(c[i][j], al[i], bh[j], c[i][j]);
                        wmma::mma_sync(c[i][j], ah[i], bl[j], c[i][j]);
                    }
            }
            pb ^= 1;
        }

        // ---- epilogue: direct global stores (M % 16 == 0) ----
        float* Y = (mSel == 0) ? Qp : KVp;
        const int ldY  = (mSel == 0) ? 128 : 256;
        const int coff = (mSel == 2) ? 128 : 0;
        #pragma unroll
        for (int i = 0; i < 2; i++) {
            const int grow = tile0 + wr * 32 + i * 16;
            if (grow + 16 <= M) {
                #pragma unroll
                for (int j = 0; j < 2; j++)
                    wmma::store_matrix_sync(Y + (size_t)grow * ldY + coff + wc * 32 + j * 16,
                                            c[i][j], ldY, wmma::mem_row_major);
            }
        }
    }
}

// ============== gather: one warp per destination, fused finalize ============
// lane l: head h = l>>3, dims (l&7)*4. Q in registers; depth-2 software
// pipeline over contiguous 1KB KV records; __expf; writes relu(num/den).
__global__ __launch_bounds__(256, 4) void gather_kernel(
    const float* __restrict__ Qu, const float* __restrict__ Qi,
    const float* __restrict__ KVu, const float* __restrict__ KVi,
    const int* __restrict__ cnt, const int* __restrict__ srt,
    float* __restrict__ out)
{
    const int g = blockIdx.x * 8 + (threadIdx.x >> 5);
    if (g >= NSEG) return;
    const int lane = threadIdx.x & 31;
    const int c4 = (lane & 7) * 4 + (lane >> 3) * 32;   // this lane's 4 dims

    float* zp = out + (size_t)g * 128 + c4;
    const int c = min(cnt[g], BCAP);
    if (c == 0) {
        *(float4*)zp = make_float4(0.f, 0.f, 0.f, 0.f);
        return;
    }

    const float* Q;
    const float* KV;
    int qrow;
    if (g < NUSER) { Q = Qu; KV = KVi; qrow = g; }
    else           { Q = Qi; KV = KVu; qrow = g - NUSER; }

    const float4 q4 = *(const float4*)(Q + (size_t)qrow * 128 + c4);
    const int st = g * BCAP;

    // depth-2 prefetch pipeline over 1KB KV records
    float4 k0, v0, k1, v1;
    {
        const float* r0 = KV + (size_t)__ldg(srt + st) * 256;
        k0 = *(const float4*)(r0 + c4);
        v0 = *(const float4*)(r0 + 128 + c4);
    }
    if (c > 1) {
        const float* r1 = KV + (size_t)__ldg(srt + st + 1) * 256;
        k1 = *(const float4*)(r1 + c4);
        v1 = *(const float4*)(r1 + 128 + c4);
    }

    float ax = 0.f, ay = 0.f, az = 0.f, aw = 0.f, den = 0.f;
    for (int j = 0; j < c; j++) {
        const float4 k4 = k0, v4 = v0;
        k0 = k1; v0 = v1;
        if (j + 2 < c) {
            const float* rn = KV + (size_t)__ldg(srt + st + j + 2) * 256;
            k1 = *(const float4*)(rn + c4);
            v1 = *(const float4*)(rn + 128 + c4);
        }
        float p = q4.x * k4.x + q4.y * k4.y + q4.z * k4.z + q4.w * k4.w;
        p += __shfl_xor_sync(0xffffffffu, p, 1);
        p += __shfl_xor_sync(0xffffffffu, p, 2);
        p += __shfl_xor_sync(0xffffffffu, p, 4);
        const float w = __expf(p);
        den += w;
        ax += w * v4.x; ay += w * v4.y; az += w * v4.z; aw += w * v4.w;
    }
    const float inv = 1.f / den;
    *(float4*)zp = make_float4(fmaxf(ax * inv, 0.f), fmaxf(ay * inv, 0.f),
                               fmaxf(az * inv, 0.f), fmaxf(aw * inv, 0.f));
}

extern "C" void kernel_launch(void* const* d_in, const int* in_sizes, int n_in,
                              void* d_out, int out_size)
{
    const float* h_user    = (const float*)d_in[0];
    const float* h_item    = (const float*)d_in[1];
    const int*   edge_user = (const int*)d_in[2];
    const int*   edge_item = (const int*)d_in[3];
    const float* u_wq = (const float*)d_in[4];
    const float* u_wk = (const float*)d_in[5];
    const float* u_wv = (const float*)d_in[6];
    const float* i_wq = (const float*)d_in[7];
    const float* i_wk = (const float*)d_in[8];
    const float* i_wv = (const float*)d_in[9];
    float* out = (float*)d_out;

    const int nE = in_sizes[2];
    const int Mu = in_sizes[0] / DIN;
    const int Mi = in_sizes[1] / DIN;

    float *Qu, *Qi, *KVu, *KVi;
    int *cnt, *srt;
    __nv_bfloat16* WB;
    cudaGetSymbolAddress((void**)&Qu, g_Qu);
    cudaGetSymbolAddress((void**)&Qi, g_Qi);
    cudaGetSymbolAddress((void**)&KVu, g_KVu);
    cudaGetSymbolAddress((void**)&KVi, g_KVi);
    cudaGetSymbolAddress((void**)&cnt, g_cnt);
    cudaGetSymbolAddress((void**)&srt, g_srt);
    cudaGetSymbolAddress((void**)&WB, g_WB);

    cudaFuncSetAttribute(proj_wmma, cudaFuncAttributeMaxDynamicSharedMemorySize, SMEM_PROJ);

    // ---- utilities: memset + (split_w || bucket) in one launch ----
    cudaMemsetAsync(cnt, 0, sizeof(int) * NSEG);
    const int eb = (2 * nE + 255) / 256;
    util_kernel<<<384 + eb, 256>>>(u_wq, u_wk, u_wv, i_wq, i_wk, i_wv, WB,
                                   edge_user, edge_item, cnt, srt, nE);

    // ---- projections (one merged launch, cp.async B pipeline) ----
    const int tilesU = (Mu + 63) / 64, tilesI = (Mi + 63) / 64;
    proj_wmma<<<tilesU + tilesI, 256, SMEM_PROJ>>>(h_user, h_item, WB,
                                                   Qu, Qi, KVu, KVi, Mu, Mi, tilesU);

    // ---- fused attention gather + softmax-normalize + relu ----
    gather_kernel<<<(NSEG + 7) / 8, 256>>>(Qu, Qi, KVu, KVi, cnt, srt, out);
}

// round 14
// speedup vs baseline: 1.1466x; 1.0434x over previous
#include <cuda_runtime.h>
#include <cuda_bf16.h>
#include <mma.h>
#include <cstdint>

using namespace nvcuda;

#define NUSER 100000
#define NITEM 50000
#define NSEG  150000            // NUSER + NITEM
#define NEDGE 400000
#define DIN 128
#define BCAP 64                 // per-destination bucket capacity (max degree ~30)

// Scratch (allocation-free rule: __device__ globals)
// Q separate [node][128]; K,V interleaved per node: [node][0:128)=K, [128:256)=V
__device__ float g_Qu[(size_t)NUSER * DIN];
__device__ float g_Qi[(size_t)NITEM * DIN];
__device__ float g_KVu[(size_t)NUSER * 256];
__device__ float g_KVi[(size_t)NITEM * 256];
__device__ int g_cnt[NSEG];
__device__ int g_srt[(size_t)NSEG * BCAP];
// pre-split weights: 6 matrices x {hi,lo} planes, logical [k][n] (n = h*32+e)
__device__ __nv_bfloat16 g_WB[6 * 2 * 128 * 128];

// ---------------- cp.async helpers (baseline sm_80 PTX) ---------------------
__device__ __forceinline__ void cp_async16(void* smem_dst, const void* gsrc) {
    const uint32_t s = (uint32_t)__cvta_generic_to_shared(smem_dst);
    asm volatile("cp.async.cg.shared.global [%0], [%1], 16;" :: "r"(s), "l"(gsrc));
}
#define CP_COMMIT() asm volatile("cp.async.commit_group;" ::: "memory")
#define CP_WAIT0()  asm volatile("cp.async.wait_group 0;" ::: "memory")

// ============ merged utility kernel: split_w (blocks 0..383) + bucket =======
__global__ __launch_bounds__(256) void util_kernel(
    const float* __restrict__ w0, const float* __restrict__ w1, const float* __restrict__ w2,
    const float* __restrict__ w3, const float* __restrict__ w4, const float* __restrict__ w5,
    __nv_bfloat16* __restrict__ WB,
    const int* __restrict__ eu, const int* __restrict__ ei,
    int* __restrict__ cnt, int* __restrict__ srt, int nE)
{
    const int bx = blockIdx.x;
    if (bx < 384) {              // ---- split_w part: 384 blocks x 256 = 6*16384
        const int m = bx >> 6;
        const float* w = m == 0 ? w0 : m == 1 ? w1 : m == 2 ? w2 : m == 3 ? w3 : m == 4 ? w4 : w5;
        __nv_bfloat16* hi = WB + (size_t)m * 2 * 16384;
        __nv_bfloat16* lo = hi + 16384;
        const int i = (bx & 63) * 256 + threadIdx.x;
        const int k = i >> 7, n = i & 127;
        const float v = w[(n >> 5) * 4096 + k * 32 + (n & 31)];
        const __nv_bfloat16 h = __float2bfloat16(v);
        hi[i] = h;
        lo[i] = __float2bfloat16(v - __bfloat162float(h));
    } else {                     // ---- bucket part
        const int t = (bx - 384) * 256 + threadIdx.x;
        if (t < nE) {
            const int d = eu[t];
            const int p = atomicAdd(&cnt[d], 1);
            if (p < BCAP) srt[(size_t)d * BCAP + p] = ei[t];
        } else if (t < 2 * nE) {
            const int e = t - nE;
            const int d = NUSER + ei[e];
            const int p = atomicAdd(&cnt[d], 1);
            if (p < BCAP) srt[(size_t)d * BCAP + p] = eu[e];
        }
    }
}

// ============ projection GEMM (merged user+item) =============================
// Y[M,128] = X[M,128] @ Wlogical[128,128], bf16 wmma 3-term split emulation.
// B staged in 64-k-row chunks (hi+lo, 32KB) via cp.async double buffering.
// Q stride 128; K/V interleaved stride 256. M % 16 == 0 holds. 2 CTAs/SM.

static constexpr int LDA = 136;   // bf16 elems (272B rows)
static constexpr int LDB = 136;
static constexpr int A_BYTES   = 2 * 64 * LDA * 2;     // 34816
static constexpr int BBUF_BYTES = 2 * 64 * LDB * 2;    // 34816 (hi 64 rows + lo 64 rows)
static constexpr int SMEM_PROJ = A_BYTES + 2 * BBUF_BYTES;  // 104448 B

__device__ __forceinline__ void issue_b_chunk(
    const __nv_bfloat16* WBs, int phase, char* bufBase, int tid)
{
    const int mSel = phase >> 1, c = phase & 1;
    const __nv_bfloat16* Wm = WBs + (size_t)mSel * 2 * 16384;
    const char* srcHi = (const char*)(Wm + c * 8192);            // 16KB contiguous
    const char* srcLo = (const char*)(Wm + 16384 + c * 8192);
    #pragma unroll
    for (int i = tid; i < 2048; i += 256) {
        const int plane = i >> 10;            // 0 = hi, 1 = lo
        const int idx = i & 1023;             // uint4 index within plane chunk
        const int r = idx >> 4, c16 = idx & 15;   // 64 rows x 16 uint4/row
        char* dst = bufBase + plane * (64 * LDB * 2) + r * (LDB * 2) + c16 * 16;
        const char* s = (plane ? srcLo : srcHi) + (size_t)idx * 16;
        cp_async16(dst, s);
    }
}

__global__ __launch_bounds__(256, 2) void proj_wmma(
    const float* __restrict__ Xu, const float* __restrict__ Xi,
    const __nv_bfloat16* __restrict__ WB,
    float* __restrict__ Qu, float* __restrict__ Qi,
    float* __restrict__ KVu, float* __restrict__ KVi,
    int Mu, int Mi, int tilesU)
{
    extern __shared__ char smraw[];
    __nv_bfloat16* Ah = (__nv_bfloat16*)smraw;          // 64 x LDA
    __nv_bfloat16* Al = Ah + 64 * LDA;
    char* bBuf[2] = { smraw + A_BYTES, smraw + A_BYTES + BBUF_BYTES };

    const int tid  = threadIdx.x;
    const int wid  = tid >> 5;
    const int lane = tid & 31;

    const bool isU = (int)blockIdx.x < tilesU;
    const int tile0 = (isU ? blockIdx.x : blockIdx.x - tilesU) * 64;
    const int M = isU ? Mu : Mi;
    const float* X = isU ? Xu : Xi;
    const __nv_bfloat16* WBs = WB + (isU ? 0 : (size_t)3 * 2 * 16384);
    float* Qp  = isU ? Qu  : Qi;
    float* KVp = isU ? KVu : KVi;

    // ---- kick off B chunk 0 immediately (overlaps X staging) ----
    issue_b_chunk(WBs, 0, bBuf[0], tid);
    CP_COMMIT();

    // ---- stage X tile ONCE -> Ah/Al (warp per row, float4 per lane) ----
    #pragma unroll
    for (int r0 = 0; r0 < 64; r0 += 8) {
        const int row = r0 + wid;
        const int grow = tile0 + row;
        float4 av = make_float4(0.f, 0.f, 0.f, 0.f);
        if (grow < M) av = *(const float4*)(X + (size_t)grow * 128 + lane * 4);
        const float vs[4] = {av.x, av.y, av.z, av.w};
        __nv_bfloat16 hb[4], lb[4];
        #pragma unroll
        for (int j = 0; j < 4; j++) {
            hb[j] = __float2bfloat16(vs[j]);
            lb[j] = __float2bfloat16(vs[j] - __bfloat162float(hb[j]));
        }
        *(uint2*)&Ah[row * LDA + lane * 4] = *(const uint2*)hb;
        *(uint2*)&Al[row * LDA + lane * 4] = *(const uint2*)lb;
    }

    const int wr = wid >> 2;          // warp row (32 rows)
    const int wc = wid & 3;           // warp col (32 cols)
    int pb = 0;                        // current B buffer

    for (int mSel = 0; mSel < 3; mSel++) {
        wmma::fragment<wmma::accumulator, 16, 16, 16, float> c[2][2];
        #pragma unroll
        for (int i = 0; i < 2; i++)
            #pragma unroll
            for (int j = 0; j < 2; j++) wmma::fill_fragment(c[i][j], 0.f);

        #pragma unroll
        for (int ch = 0; ch < 2; ch++) {
            const int phase = mSel * 2 + ch;
            CP_WAIT0();          // our chunk `phase` is in
            __syncthreads();     // all threads' chunk in; all done reading other buf
            if (phase + 1 < 6) {
                issue_b_chunk(WBs, phase + 1, bBuf[pb ^ 1], tid);
                CP_COMMIT();
            }
            const __nv_bfloat16* BhB = (const __nv_bfloat16*)bBuf[pb];
            const __nv_bfloat16* BlB = BhB + 64 * LDB;
            const int kBase = ch * 64;

            #pragma unroll
            for (int kk = 0; kk < 64; kk += 16) {
                wmma::fragment<wmma::matrix_a, 16, 16, 16, __nv_bfloat16, wmma::row_major> ah[2], al[2];
                wmma::fragment<wmma::matrix_b, 16, 16, 16, __nv_bfloat16, wmma::row_major> bh[2], bl[2];
                #pragma unroll
                for (int i = 0; i < 2; i++) {
                    wmma::load_matrix_sync(ah[i], Ah + (wr * 32 + i * 16) * LDA + kBase + kk, LDA);
                    wmma::load_matrix_sync(al[i], Al + (wr * 32 + i * 16) * LDA + kBase + kk, LDA);
                }
                #pragma unroll
                for (int j = 0; j < 2; j++) {
                    wmma::load_matrix_sync(bh[j], BhB + kk * LDB + wc * 32 + j * 16, LDB);
                    wmma::load_matrix_sync(bl[j], BlB + kk * LDB + wc * 32 + j * 16, LDB);
                }
                #pragma unroll
                for (int i = 0; i < 2; i++)
                    #pragma unroll
                    for (int j = 0; j < 2; j++) {
                        wmma::mma_sync(c[i][j], ah[i], bh[j], c[i][j]);
                        wmma::mma_sync(c[i][j], al[i], bh[j], c[i][j]);
                        wmma::mma_sync(c[i][j], ah[i], bl[j], c[i][j]);
                    }
            }
            pb ^= 1;
        }

        // ---- epilogue: direct global stores (M % 16 == 0) ----
        float* Y = (mSel == 0) ? Qp : KVp;
        const int ldY  = (mSel == 0) ? 128 : 256;
        const int coff = (mSel == 2) ? 128 : 0;
        #pragma unroll
        for (int i = 0; i < 2; i++) {
            const int grow = tile0 + wr * 32 + i * 16;
            if (grow + 16 <= M) {
                #pragma unroll
                for (int j = 0; j < 2; j++)
                    wmma::store_matrix_sync(Y + (size_t)grow * ldY + coff + wc * 32 + j * 16,
                                            c[i][j], ldY, wmma::mem_row_major);
            }
        }
    }
}

// ============== gather: one warp per destination, fused finalize ============
// 64-thread CTAs (2 warps) so a high-degree straggler warp holds only one
// sibling's slots, not 7 — raises achieved occupancy. Q read streaming
// (__ldcs), output written streaming (__stcs) to keep KV resident in L2.
__global__ __launch_bounds__(64, 16) void gather_kernel(
    const float* __restrict__ Qu, const float* __restrict__ Qi,
    const float* __restrict__ KVu, const float* __restrict__ KVi,
    const int* __restrict__ cnt, const int* __restrict__ srt,
    float* __restrict__ out)
{
    const int g = blockIdx.x * 2 + (threadIdx.x >> 5);
    if (g >= NSEG) return;
    const int lane = threadIdx.x & 31;
    const int c4 = (lane & 7) * 4 + (lane >> 3) * 32;   // this lane's 4 dims

    float* zp = out + (size_t)g * 128 + c4;
    const int c = min(cnt[g], BCAP);
    if (c == 0) {
        __stcs((float4*)zp, make_float4(0.f, 0.f, 0.f, 0.f));
        return;
    }

    const float* Q;
    const float* KV;
    int qrow;
    if (g < NUSER) { Q = Qu; KV = KVi; qrow = g; }
    else           { Q = Qi; KV = KVu; qrow = g - NUSER; }

    const float4 q4 = __ldcs((const float4*)(Q + (size_t)qrow * 128 + c4));
    const int st = g * BCAP;

    // depth-2 prefetch pipeline over 1KB KV records
    float4 k0, v0, k1, v1;
    {
        const float* r0 = KV + (size_t)__ldg(srt + st) * 256;
        k0 = *(const float4*)(r0 + c4);
        v0 = *(const float4*)(r0 + 128 + c4);
    }
    if (c > 1) {
        const float* r1 = KV + (size_t)__ldg(srt + st + 1) * 256;
        k1 = *(const float4*)(r1 + c4);
        v1 = *(const float4*)(r1 + 128 + c4);
    }

    float ax = 0.f, ay = 0.f, az = 0.f, aw = 0.f, den = 0.f;
    for (int j = 0; j < c; j++) {
        const float4 k4 = k0, v4 = v0;
        k0 = k1; v0 = v1;
        if (j + 2 < c) {
            const float* rn = KV + (size_t)__ldg(srt + st + j + 2) * 256;
            k1 = *(const float4*)(rn + c4);
            v1 = *(const float4*)(rn + 128 + c4);
        }
        float p = q4.x * k4.x + q4.y * k4.y + q4.z * k4.z + q4.w * k4.w;
        p += __shfl_xor_sync(0xffffffffu, p, 1);
        p += __shfl_xor_sync(0xffffffffu, p, 2);
        p += __shfl_xor_sync(0xffffffffu, p, 4);
        const float w = __expf(p);
        den += w;
        ax += w * v4.x; ay += w * v4.y; az += w * v4.z; aw += w * v4.w;
    }
    const float inv = 1.f / den;
    __stcs((float4*)zp, make_float4(fmaxf(ax * inv, 0.f), fmaxf(ay * inv, 0.f),
                                    fmaxf(az * inv, 0.f), fmaxf(aw * inv, 0.f)));
}

extern "C" void kernel_launch(void* const* d_in, const int* in_sizes, int n_in,
                              void* d_out, int out_size)
{
    const float* h_user    = (const float*)d_in[0];
    const float* h_item    = (const float*)d_in[1];
    const int*   edge_user = (const int*)d_in[2];
    const int*   edge_item = (const int*)d_in[3];
    const float* u_wq = (const float*)d_in[4];
    const float* u_wk = (const float*)d_in[5];
    const float* u_wv = (const float*)d_in[6];
    const float* i_wq = (const float*)d_in[7];
    const float* i_wk = (const float*)d_in[8];
    const float* i_wv = (const float*)d_in[9];
    float* out = (float*)d_out;

    const int nE = in_sizes[2];
    const int Mu = in_sizes[0] / DIN;
    const int Mi = in_sizes[1] / DIN;

    float *Qu, *Qi, *KVu, *KVi;
    int *cnt, *srt;
    __nv_bfloat16* WB;
    cudaGetSymbolAddress((void**)&Qu, g_Qu);
    cudaGetSymbolAddress((void**)&Qi, g_Qi);
    cudaGetSymbolAddress((void**)&KVu, g_KVu);
    cudaGetSymbolAddress((void**)&KVi, g_KVi);
    cudaGetSymbolAddress((void**)&cnt, g_cnt);
    cudaGetSymbolAddress((void**)&srt, g_srt);
    cudaGetSymbolAddress((void**)&WB, g_WB);

    cudaFuncSetAttribute(proj_wmma, cudaFuncAttributeMaxDynamicSharedMemorySize, SMEM_PROJ);

    // ---- utilities: memset + (split_w || bucket) in one launch ----
    cudaMemsetAsync(cnt, 0, sizeof(int) * NSEG);
    const int eb = (2 * nE + 255) / 256;
    util_kernel<<<384 + eb, 256>>>(u_wq, u_wk, u_wv, i_wq, i_wk, i_wv, WB,
                                   edge_user, edge_item, cnt, srt, nE);

    // ---- projections (one merged launch, cp.async B pipeline) ----
    const int tilesU = (Mu + 63) / 64, tilesI = (Mi + 63) / 64;
    proj_wmma<<<tilesU + tilesI, 256, SMEM_PROJ>>>(h_user, h_item, WB,
                                                   Qu, Qi, KVu, KVi, Mu, Mi, tilesU);

    // ---- fused attention gather + softmax-normalize + relu ----
    gather_kernel<<<(NSEG + 1) / 2, 64>>>(Qu, Qi, KVu, KVi, cnt, srt, out);
}

// round 15
// speedup vs baseline: 1.1483x; 1.0015x over previous
#include <cuda_runtime.h>
#include <cuda_bf16.h>
#include <mma.h>
#include <cstdint>

using namespace nvcuda;

#define NUSER 100000
#define NITEM 50000
#define NSEG  150000            // NUSER + NITEM
#define NEDGE 400000
#define DIN 128
#define BCAP 64                 // per-destination bucket capacity (max degree ~30)

// Scratch (allocation-free rule: __device__ globals)
// Q separate [node][128]; K,V interleaved per node: [node][0:128)=K, [128:256)=V
__device__ float g_Qu[(size_t)NUSER * DIN];
__device__ float g_Qi[(size_t)NITEM * DIN];
__device__ float g_KVu[(size_t)NUSER * 256];
__device__ float g_KVi[(size_t)NITEM * 256];
__device__ int g_cnt[NSEG];
__device__ int g_srt[(size_t)NSEG * BCAP];
// pre-split weights: 6 matrices x {hi,lo} planes, logical [k][n] (n = h*32+e)
__device__ __nv_bfloat16 g_WB[6 * 2 * 128 * 128];

// ---------------- cp.async helpers (baseline sm_80 PTX) ---------------------
__device__ __forceinline__ void cp_async16(void* smem_dst, const void* gsrc) {
    const uint32_t s = (uint32_t)__cvta_generic_to_shared(smem_dst);
    asm volatile("cp.async.cg.shared.global [%0], [%1], 16;" :: "r"(s), "l"(gsrc));
}
#define CP_COMMIT() asm volatile("cp.async.commit_group;" ::: "memory")
#define CP_WAIT0()  asm volatile("cp.async.wait_group 0;" ::: "memory")

// ---------------- W pre-split: fp32 [h][k][e] -> bf16 hi/lo [k][n] ----------
__global__ __launch_bounds__(256) void split_w_kernel(
    const float* __restrict__ w0, const float* __restrict__ w1, const float* __restrict__ w2,
    const float* __restrict__ w3, const float* __restrict__ w4, const float* __restrict__ w5,
    __nv_bfloat16* __restrict__ WB)
{
    const int bx = blockIdx.x;                       // 384 blocks = 6 * 64
    const int m = bx >> 6;
    const float* w = m == 0 ? w0 : m == 1 ? w1 : m == 2 ? w2 : m == 3 ? w3 : m == 4 ? w4 : w5;
    __nv_bfloat16* hi = WB + (size_t)m * 2 * 16384;
    __nv_bfloat16* lo = hi + 16384;
    const int i = (bx & 63) * 256 + threadIdx.x;
    const int k = i >> 7, n = i & 127;
    const float v = w[(n >> 5) * 4096 + k * 32 + (n & 31)];
    const __nv_bfloat16 h = __float2bfloat16(v);
    hi[i] = h;
    lo[i] = __float2bfloat16(v - __bfloat162float(h));
}

// ============ projection GEMM (merged user+item) + hidden bucket scatter ====
// Y[M,128] = X[M,128] @ Wlogical[128,128], bf16 wmma 3-term split emulation.
// B staged in 64-k-row chunks (hi+lo, 32KB) via cp.async double buffering.
// Each CTA additionally scatters a slice of edges into the destination
// buckets AFTER its X staging — hidden under the in-flight cp.async/LDG
// latency. Gather launches after proj, so bucket completion is guaranteed.
// Q stride 128; K/V interleaved stride 256. M % 16 == 0 holds. 2 CTAs/SM.

static constexpr int LDA = 136;   // bf16 elems (272B rows)
static constexpr int LDB = 136;
static constexpr int A_BYTES   = 2 * 64 * LDA * 2;     // 34816
static constexpr int BBUF_BYTES = 2 * 64 * LDB * 2;    // 34816 (hi 64 + lo 64 rows)
static constexpr int SMEM_PROJ = A_BYTES + 2 * BBUF_BYTES;  // 104448 B

__device__ __forceinline__ void issue_b_chunk(
    const __nv_bfloat16* WBs, int phase, char* bufBase, int tid)
{
    const int mSel = phase >> 1, c = phase & 1;
    const __nv_bfloat16* Wm = WBs + (size_t)mSel * 2 * 16384;
    const char* srcHi = (const char*)(Wm + c * 8192);            // 16KB contiguous
    const char* srcLo = (const char*)(Wm + 16384 + c * 8192);
    #pragma unroll
    for (int i = tid; i < 2048; i += 256) {
        const int plane = i >> 10;            // 0 = hi, 1 = lo
        const int idx = i & 1023;             // uint4 index within plane chunk
        const int r = idx >> 4, c16 = idx & 15;   // 64 rows x 16 uint4/row
        char* dst = bufBase + plane * (64 * LDB * 2) + r * (LDB * 2) + c16 * 16;
        const char* s = (plane ? srcLo : srcHi) + (size_t)idx * 16;
        cp_async16(dst, s);
    }
}

__global__ __launch_bounds__(256, 2) void proj_wmma(
    const float* __restrict__ Xu, const float* __restrict__ Xi,
    const __nv_bfloat16* __restrict__ WB,
    float* __restrict__ Qu, float* __restrict__ Qi,
    float* __restrict__ KVu, float* __restrict__ KVi,
    int Mu, int Mi, int tilesU,
    const int* __restrict__ eu, const int* __restrict__ ei,
    int* __restrict__ cnt, int* __restrict__ srt, int nE, int chunkE)
{
    extern __shared__ char smraw[];
    __nv_bfloat16* Ah = (__nv_bfloat16*)smraw;          // 64 x LDA
    __nv_bfloat16* Al = Ah + 64 * LDA;
    char* bBuf[2] = { smraw + A_BYTES, smraw + A_BYTES + BBUF_BYTES };

    const int tid  = threadIdx.x;
    const int wid  = tid >> 5;
    const int lane = tid & 31;

    const bool isU = (int)blockIdx.x < tilesU;
    const int tile0 = (isU ? blockIdx.x : blockIdx.x - tilesU) * 64;
    const int M = isU ? Mu : Mi;
    const float* X = isU ? Xu : Xi;
    const __nv_bfloat16* WBs = WB + (isU ? 0 : (size_t)3 * 2 * 16384);
    float* Qp  = isU ? Qu  : Qi;
    float* KVp = isU ? KVu : KVi;

    // ---- kick off B chunk 0 immediately (overlaps X staging) ----
    issue_b_chunk(WBs, 0, bBuf[0], tid);
    CP_COMMIT();

    // ---- stage X tile ONCE -> Ah/Al (warp per row, float4 per lane) ----
    #pragma unroll
    for (int r0 = 0; r0 < 64; r0 += 8) {
        const int row = r0 + wid;
        const int grow = tile0 + row;
        float4 av = make_float4(0.f, 0.f, 0.f, 0.f);
        if (grow < M) av = *(const float4*)(X + (size_t)grow * 128 + lane * 4);
        const float vs[4] = {av.x, av.y, av.z, av.w};
        __nv_bfloat16 hb[4], lb[4];
        #pragma unroll
        for (int j = 0; j < 4; j++) {
            hb[j] = __float2bfloat16(vs[j]);
            lb[j] = __float2bfloat16(vs[j] - __bfloat162float(hb[j]));
        }
        *(uint2*)&Ah[row * LDA + lane * 4] = *(const uint2*)hb;
        *(uint2*)&Al[row * LDA + lane * 4] = *(const uint2*)lb;
    }

    // ---- hidden bucket scatter: slice of edges, overlaps cp.async latency --
    {
        const int base = blockIdx.x * chunkE;
        const int end  = min(base + chunkE, 2 * nE);
        for (int t = base + tid; t < end; t += 256) {
            if (t < nE) {
                const int d = eu[t];
                const int p = atomicAdd(&cnt[d], 1);
                if (p < BCAP) srt[(size_t)d * BCAP + p] = ei[t];
            } else {
                const int e = t - nE;
                const int d = NUSER + ei[e];
                const int p = atomicAdd(&cnt[d], 1);
                if (p < BCAP) srt[(size_t)d * BCAP + p] = eu[e];
            }
        }
    }

    const int wr = wid >> 2;          // warp row (32 rows)
    const int wc = wid & 3;           // warp col (32 cols)
    int pb = 0;                        // current B buffer

    for (int mSel = 0; mSel < 3; mSel++) {
        wmma::fragment<wmma::accumulator, 16, 16, 16, float> c[2][2];
        #pragma unroll
        for (int i = 0; i < 2; i++)
            #pragma unroll
            for (int j = 0; j < 2; j++) wmma::fill_fragment(c[i][j], 0.f);

        #pragma unroll
        for (int ch = 0; ch < 2; ch++) {
            const int phase = mSel * 2 + ch;
            CP_WAIT0();          // our chunk `phase` is in
            __syncthreads();     // all threads' chunk in; all done reading other buf
            if (phase + 1 < 6) {
                issue_b_chunk(WBs, phase + 1, bBuf[pb ^ 1], tid);
                CP_COMMIT();
            }
            const __nv_bfloat16* BhB = (const __nv_bfloat16*)bBuf[pb];
            const __nv_bfloat16* BlB = BhB + 64 * LDB;
            const int kBase = ch * 64;

            #pragma unroll
            for (int kk = 0; kk < 64; kk += 16) {
                wmma::fragment<wmma::matrix_a, 16, 16, 16, __nv_bfloat16, wmma::row_major> ah[2], al[2];
                wmma::fragment<wmma::matrix_b, 16, 16, 16, __nv_bfloat16, wmma::row_major> bh[2], bl[2];
                #pragma unroll
                for (int i = 0; i < 2; i++) {
                    wmma::load_matrix_sync(ah[i], Ah + (wr * 32 + i * 16) * LDA + kBase + kk, LDA);
                    wmma::load_matrix_sync(al[i], Al + (wr * 32 + i * 16) * LDA + kBase + kk, LDA);
                }
                #pragma unroll
                for (int j = 0; j < 2; j++) {
                    wmma::load_matrix_sync(bh[j], BhB + kk * LDB + wc * 32 + j * 16, LDB);
                    wmma::load_matrix_sync(bl[j], BlB + kk * LDB + wc * 32 + j * 16, LDB);
                }
                #pragma unroll
                for (int i = 0; i < 2; i++)
                    #pragma unroll
                    for (int j = 0; j < 2; j++) {
                        wmma::mma_sync(c[i][j], ah[i], bh[j], c[i][j]);
                        wmma::mma_sync(c[i][j], al[i], bh[j], c[i][j]);
                        wmma::mma_sync(c[i][j], ah[i], bl[j], c[i][j]);
                    }
            }
            pb ^= 1;
        }

        // ---- epilogue: direct global stores (M % 16 == 0) ----
        float* Y = (mSel == 0) ? Qp : KVp;
        const int ldY  = (mSel == 0) ? 128 : 256;
        const int coff = (mSel == 2) ? 128 : 0;
        #pragma unroll
        for (int i = 0; i < 2; i++) {
            const int grow = tile0 + wr * 32 + i * 16;
            if (grow + 16 <= M) {
                #pragma unroll
                for (int j = 0; j < 2; j++)
                    wmma::store_matrix_sync(Y + (size_t)grow * ldY + coff + wc * 32 + j * 16,
                                            c[i][j], ldY, wmma::mem_row_major);
            }
        }
    }
}

// ============== gather: one warp per destination, fused finalize ============
// 64-thread CTAs (2 warps): straggler warp holds only 1 sibling. Q read
// streaming (__ldcs), output streaming (__stcs) to keep KV resident in L2.
__global__ __launch_bounds__(64, 16) void gather_kernel(
    const float* __restrict__ Qu, const float* __restrict__ Qi,
    const float* __restrict__ KVu, const float* __restrict__ KVi,
    const int* __restrict__ cnt, const int* __restrict__ srt,
    float* __restrict__ out)
{
    const int g = blockIdx.x * 2 + (threadIdx.x >> 5);
    if (g >= NSEG) return;
    const int lane = threadIdx.x & 31;
    const int c4 = (lane & 7) * 4 + (lane >> 3) * 32;   // this lane's 4 dims

    float* zp = out + (size_t)g * 128 + c4;
    const int c = min(cnt[g], BCAP);
    if (c == 0) {
        __stcs((float4*)zp, make_float4(0.f, 0.f, 0.f, 0.f));
        return;
    }

    const float* Q;
    const float* KV;
    int qrow;
    if (g < NUSER) { Q = Qu; KV = KVi; qrow = g; }
    else           { Q = Qi; KV = KVu; qrow = g - NUSER; }

    const float4 q4 = __ldcs((const float4*)(Q + (size_t)qrow * 128 + c4));
    const int st = g * BCAP;

    // depth-2 prefetch pipeline over 1KB KV records
    float4 k0, v0, k1, v1;
    {
        const float* r0 = KV + (size_t)__ldg(srt + st) * 256;
        k0 = *(const float4*)(r0 + c4);
        v0 = *(const float4*)(r0 + 128 + c4);
    }
    if (c > 1) {
        const float* r1 = KV + (size_t)__ldg(srt + st + 1) * 256;
        k1 = *(const float4*)(r1 + c4);
        v1 = *(const float4*)(r1 + 128 + c4);
    }

    float ax = 0.f, ay = 0.f, az = 0.f, aw = 0.f, den = 0.f;
    for (int j = 0; j < c; j++) {
        const float4 k4 = k0, v4 = v0;
        k0 = k1; v0 = v1;
        if (j + 2 < c) {
            const float* rn = KV + (size_t)__ldg(srt + st + j + 2) * 256;
            k1 = *(const float4*)(rn + c4);
            v1 = *(const float4*)(rn + 128 + c4);
        }
        float p = q4.x * k4.x + q4.y * k4.y + q4.z * k4.z + q4.w * k4.w;
        p += __shfl_xor_sync(0xffffffffu, p, 1);
        p += __shfl_xor_sync(0xffffffffu, p, 2);
        p += __shfl_xor_sync(0xffffffffu, p, 4);
        const float w = __expf(p);
        den += w;
        ax += w * v4.x; ay += w * v4.y; az += w * v4.z; aw += w * v4.w;
    }
    const float inv = 1.f / den;
    __stcs((float4*)zp, make_float4(fmaxf(ax * inv, 0.f), fmaxf(ay * inv, 0.f),
                                    fmaxf(az * inv, 0.f), fmaxf(aw * inv, 0.f)));
}

extern "C" void kernel_launch(void* const* d_in, const int* in_sizes, int n_in,
                              void* d_out, int out_size)
{
    const float* h_user    = (const float*)d_in[0];
    const float* h_item    = (const float*)d_in[1];
    const int*   edge_user = (const int*)d_in[2];
    const int*   edge_item = (const int*)d_in[3];
    const float* u_wq = (const float*)d_in[4];
    const float* u_wk = (const float*)d_in[5];
    const float* u_wv = (const float*)d_in[6];
    const float* i_wq = (const float*)d_in[7];
    const float* i_wk = (const float*)d_in[8];
    const float* i_wv = (const float*)d_in[9];
    float* out = (float*)d_out;

    const int nE = in_sizes[2];
    const int Mu = in_sizes[0] / DIN;
    const int Mi = in_sizes[1] / DIN;

    float *Qu, *Qi, *KVu, *KVi;
    int *cnt, *srt;
    __nv_bfloat16* WB;
    cudaGetSymbolAddress((void**)&Qu, g_Qu);
    cudaGetSymbolAddress((void**)&Qi, g_Qi);
    cudaGetSymbolAddress((void**)&KVu, g_KVu);
    cudaGetSymbolAddress((void**)&KVi, g_KVi);
    cudaGetSymbolAddress((void**)&cnt, g_cnt);
    cudaGetSymbolAddress((void**)&srt, g_srt);
    cudaGetSymbolAddress((void**)&WB, g_WB);

    cudaFuncSetAttribute(proj_wmma, cudaFuncAttributeMaxDynamicSharedMemorySize, SMEM_PROJ);

    // ---- memset cnt + split_w (tiny) ----
    cudaMemsetAsync(cnt, 0, sizeof(int) * NSEG);
    split_w_kernel<<<384, 256>>>(u_wq, u_wk, u_wv, i_wq, i_wk, i_wv, WB);

    // ---- projections + hidden bucket scatter (one merged launch) ----
    const int tilesU = (Mu + 63) / 64, tilesI = (Mi + 63) / 64;
    const int tilesT = tilesU + tilesI;
    const int chunkE = (2 * nE + tilesT - 1) / tilesT;
    proj_wmma<<<tilesT, 256, SMEM_PROJ>>>(h_user, h_item, WB,
                                          Qu, Qi, KVu, KVi, Mu, Mi, tilesU,
                                          edge_user, edge_item, cnt, srt, nE, chunkE);

    // ---- fused attention gather + softmax-normalize + relu ----
    gather_kernel<<<(NSEG + 1) / 2, 64>>>(Qu, Qi, KVu, KVi, cnt, srt, out);
}

// round 16
// speedup vs baseline: 1.1502x; 1.0017x over previous
#include <cuda_runtime.h>
#include <cuda_bf16.h>
#include <mma.h>
#include <cstdint>

using namespace nvcuda;

#define NUSER 100000
#define NITEM 50000
#define NSEG  150000            // NUSER + NITEM
#define NEDGE 400000
#define DIN 128
#define BCAP 64                 // per-destination bucket capacity (max degree ~30)

// Scratch (allocation-free rule: __device__ globals)
// Q separate [node][128]; K,V interleaved per node: [node][0:128)=K, [128:256)=V
__device__ float g_Qu[(size_t)NUSER * DIN];
__device__ float g_Qi[(size_t)NITEM * DIN];
__device__ float g_KVu[(size_t)NUSER * 256];
__device__ float g_KVi[(size_t)NITEM * 256];
__device__ int g_cnt[NSEG];
__device__ int g_srt[(size_t)NSEG * BCAP];
// pre-split weights: 6 matrices x {hi,lo} planes, logical [k][n] (n = h*32+e)
__device__ __nv_bfloat16 g_WB[6 * 2 * 128 * 128];

// ---------------- cp.async helpers (baseline sm_80 PTX) ---------------------
__device__ __forceinline__ void cp_async16(void* smem_dst, const void* gsrc) {
    const uint32_t s = (uint32_t)__cvta_generic_to_shared(smem_dst);
    asm volatile("cp.async.cg.shared.global [%0], [%1], 16;" :: "r"(s), "l"(gsrc));
}
#define CP_COMMIT() asm volatile("cp.async.commit_group;" ::: "memory")
#define CP_WAIT0()  asm volatile("cp.async.wait_group 0;" ::: "memory")

// ---------------- W pre-split: fp32 [h][k][e] -> bf16 hi/lo [k][n] ----------
__global__ __launch_bounds__(256) void split_w_kernel(
    const float* __restrict__ w0, const float* __restrict__ w1, const float* __restrict__ w2,
    const float* __restrict__ w3, const float* __restrict__ w4, const float* __restrict__ w5,
    __nv_bfloat16* __restrict__ WB)
{
    const int bx = blockIdx.x;                       // 384 blocks = 6 * 64
    const int m = bx >> 6;
    const float* w = m == 0 ? w0 : m == 1 ? w1 : m == 2 ? w2 : m == 3 ? w3 : m == 4 ? w4 : w5;
    __nv_bfloat16* hi = WB + (size_t)m * 2 * 16384;
    __nv_bfloat16* lo = hi + 16384;
    const int i = (bx & 63) * 256 + threadIdx.x;
    const int k = i >> 7, n = i & 127;
    const float v = w[(n >> 5) * 4096 + k * 32 + (n & 31)];
    const __nv_bfloat16 h = __float2bfloat16(v);
    hi[i] = h;
    lo[i] = __float2bfloat16(v - __bfloat162float(h));
}

// ============ projection GEMM (merged user+item) + hidden bucket scatter ====
// Y[M,128] = X[M,128] @ Wlogical[128,128], bf16 wmma 3-term split emulation.
// 128 threads = 4 warps in 2x2, warp tile 32x64: 12 fragment loads per
// 24 MMAs per k-step (0.5 loads/MMA). B staged in 64-k-row chunks via
// cp.async double buffering. Bucket scatter slice hidden after X staging.
// Q stride 128; K/V interleaved stride 256. M % 16 == 0 holds. 2 CTAs/SM.

static constexpr int LDA = 136;   // bf16 elems (272B rows)
static constexpr int LDB = 136;
static constexpr int A_BYTES   = 2 * 64 * LDA * 2;     // 34816
static constexpr int BBUF_BYTES = 2 * 64 * LDB * 2;    // 34816 (hi 64 + lo 64 rows)
static constexpr int SMEM_PROJ = A_BYTES + 2 * BBUF_BYTES;  // 104448 B

__device__ __forceinline__ void issue_b_chunk(
    const __nv_bfloat16* WBs, int phase, char* bufBase, int tid)
{
    const int mSel = phase >> 1, c = phase & 1;
    const __nv_bfloat16* Wm = WBs + (size_t)mSel * 2 * 16384;
    const char* srcHi = (const char*)(Wm + c * 8192);            // 16KB contiguous
    const char* srcLo = (const char*)(Wm + 16384 + c * 8192);
    #pragma unroll
    for (int i = tid; i < 2048; i += 128) {
        const int plane = i >> 10;            // 0 = hi, 1 = lo
        const int idx = i & 1023;             // uint4 index within plane chunk
        const int r = idx >> 4, c16 = idx & 15;   // 64 rows x 16 uint4/row
        char* dst = bufBase + plane * (64 * LDB * 2) + r * (LDB * 2) + c16 * 16;
        const char* s = (plane ? srcLo : srcHi) + (size_t)idx * 16;
        cp_async16(dst, s);
    }
}

__global__ __launch_bounds__(128, 2) void proj_wmma(
    const float* __restrict__ Xu, const float* __restrict__ Xi,
    const __nv_bfloat16* __restrict__ WB,
    float* __restrict__ Qu, float* __restrict__ Qi,
    float* __restrict__ KVu, float* __restrict__ KVi,
    int Mu, int Mi, int tilesU,
    const int* __restrict__ eu, const int* __restrict__ ei,
    int* __restrict__ cnt, int* __restrict__ srt, int nE, int chunkE)
{
    extern __shared__ char smraw[];
    __nv_bfloat16* Ah = (__nv_bfloat16*)smraw;          // 64 x LDA
    __nv_bfloat16* Al = Ah + 64 * LDA;
    char* bBuf[2] = { smraw + A_BYTES, smraw + A_BYTES + BBUF_BYTES };

    const int tid  = threadIdx.x;
    const int wid  = tid >> 5;
    const int lane = tid & 31;

    const bool isU = (int)blockIdx.x < tilesU;
    const int tile0 = (isU ? blockIdx.x : blockIdx.x - tilesU) * 64;
    const int M = isU ? Mu : Mi;
    const float* X = isU ? Xu : Xi;
    const __nv_bfloat16* WBs = WB + (isU ? 0 : (size_t)3 * 2 * 16384);
    float* Qp  = isU ? Qu  : Qi;
    float* KVp = isU ? KVu : KVi;

    // ---- kick off B chunk 0 immediately (overlaps X staging) ----
    issue_b_chunk(WBs, 0, bBuf[0], tid);
    CP_COMMIT();

    // ---- stage X tile ONCE -> Ah/Al (warp per row, float4 per lane) ----
    #pragma unroll
    for (int r0 = 0; r0 < 64; r0 += 4) {
        const int row = r0 + wid;
        const int grow = tile0 + row;
        float4 av = make_float4(0.f, 0.f, 0.f, 0.f);
        if (grow < M) av = *(const float4*)(X + (size_t)grow * 128 + lane * 4);
        const float vs[4] = {av.x, av.y, av.z, av.w};
        __nv_bfloat16 hb[4], lb[4];
        #pragma unroll
        for (int j = 0; j < 4; j++) {
            hb[j] = __float2bfloat16(vs[j]);
            lb[j] = __float2bfloat16(vs[j] - __bfloat162float(hb[j]));
        }
        *(uint2*)&Ah[row * LDA + lane * 4] = *(const uint2*)hb;
        *(uint2*)&Al[row * LDA + lane * 4] = *(const uint2*)lb;
    }

    // ---- hidden bucket scatter: slice of edges, overlaps cp.async latency --
    {
        const int base = blockIdx.x * chunkE;
        const int end  = min(base + chunkE, 2 * nE);
        for (int t = base + tid; t < end; t += 128) {
            if (t < nE) {
                const int d = eu[t];
                const int p = atomicAdd(&cnt[d], 1);
                if (p < BCAP) srt[(size_t)d * BCAP + p] = ei[t];
            } else {
                const int e = t - nE;
                const int d = NUSER + ei[e];
                const int p = atomicAdd(&cnt[d], 1);
                if (p < BCAP) srt[(size_t)d * BCAP + p] = eu[e];
            }
        }
    }

    const int wr = wid >> 1;          // warp row (32 rows)
    const int wc = wid & 1;           // warp col (64 cols)
    int pb = 0;                        // current B buffer

    for (int mSel = 0; mSel < 3; mSel++) {
        wmma::fragment<wmma::accumulator, 16, 16, 16, float> c[2][4];
        #pragma unroll
        for (int i = 0; i < 2; i++)
            #pragma unroll
            for (int j = 0; j < 4; j++) wmma::fill_fragment(c[i][j], 0.f);

        #pragma unroll
        for (int ch = 0; ch < 2; ch++) {
            const int phase = mSel * 2 + ch;
            CP_WAIT0();          // our chunk `phase` is in
            __syncthreads();     // all threads' chunk in; all done reading other buf
            if (phase + 1 < 6) {
                issue_b_chunk(WBs, phase + 1, bBuf[pb ^ 1], tid);
                CP_COMMIT();
            }
            const __nv_bfloat16* BhB = (const __nv_bfloat16*)bBuf[pb];
            const __nv_bfloat16* BlB = BhB + 64 * LDB;
            const int kBase = ch * 64;

            #pragma unroll
            for (int kk = 0; kk < 64; kk += 16) {
                wmma::fragment<wmma::matrix_a, 16, 16, 16, __nv_bfloat16, wmma::row_major> ah[2], al[2];
                #pragma unroll
                for (int i = 0; i < 2; i++) {
                    wmma::load_matrix_sync(ah[i], Ah + (wr * 32 + i * 16) * LDA + kBase + kk, LDA);
                    wmma::load_matrix_sync(al[i], Al + (wr * 32 + i * 16) * LDA + kBase + kk, LDA);
                }
                #pragma unroll
                for (int j = 0; j < 4; j++) {
                    wmma::fragment<wmma::matrix_b, 16, 16, 16, __nv_bfloat16, wmma::row_major> bh, bl;
                    wmma::load_matrix_sync(bh, BhB + kk * LDB + wc * 64 + j * 16, LDB);
                    wmma::load_matrix_sync(bl, BlB + kk * LDB + wc * 64 + j * 16, LDB);
                    #pragma unroll
                    for (int i = 0; i < 2; i++) {
                        wmma::mma_sync(c[i][j], ah[i], bh, c[i][j]);
                        wmma::mma_sync(c[i][j], al[i], bh, c[i][j]);
                        wmma::mma_sync(c[i][j], ah[i], bl, c[i][j]);
                    }
                }
            }
            pb ^= 1;
        }

        // ---- epilogue: direct global stores (M % 16 == 0) ----
        float* Y = (mSel == 0) ? Qp : KVp;
        const int ldY  = (mSel == 0) ? 128 : 256;
        const int coff = (mSel == 2) ? 128 : 0;
        #pragma unroll
        for (int i = 0; i < 2; i++) {
            const int grow = tile0 + wr * 32 + i * 16;
            if (grow + 16 <= M) {
                #pragma unroll
                for (int j = 0; j < 4; j++)
                    wmma::store_matrix_sync(Y + (size_t)grow * ldY + coff + wc * 64 + j * 16,
                                            c[i][j], ldY, wmma::mem_row_major);
            }
        }
    }
}

// ============== gather: one warp per destination, fused finalize ============
// 64-thread CTAs (2 warps): straggler warp holds only 1 sibling. Q read
// streaming (__ldcs), output streaming (__stcs) to keep KV resident in L2.
__global__ __launch_bounds__(64, 16) void gather_kernel(
    const float* __restrict__ Qu, const float* __restrict__ Qi,
    const float* __restrict__ KVu, const float* __restrict__ KVi,
    const int* __restrict__ cnt, const int* __restrict__ srt,
    float* __restrict__ out)
{
    const int g = blockIdx.x * 2 + (threadIdx.x >> 5);
    if (g >= NSEG) return;
    const int lane = threadIdx.x & 31;
    const int c4 = (lane & 7) * 4 + (lane >> 3) * 32;   // this lane's 4 dims

    float* zp = out + (size_t)g * 128 + c4;
    const int c = min(cnt[g], BCAP);
    if (c == 0) {
        __stcs((float4*)zp, make_float4(0.f, 0.f, 0.f, 0.f));
        return;
    }

    const float* Q;
    const float* KV;
    int qrow;
    if (g < NUSER) { Q = Qu; KV = KVi; qrow = g; }
    else           { Q = Qi; KV = KVu; qrow = g - NUSER; }

    const float4 q4 = __ldcs((const float4*)(Q + (size_t)qrow * 128 + c4));
    const int st = g * BCAP;

    // depth-2 prefetch pipeline over 1KB KV records
    float4 k0, v0, k1, v1;
    {
        const float* r0 = KV + (size_t)__ldg(srt + st) * 256;
        k0 = *(const float4*)(r0 + c4);
        v0 = *(const float4*)(r0 + 128 + c4);
    }
    if (c > 1) {
        const float* r1 = KV + (size_t)__ldg(srt + st + 1) * 256;
        k1 = *(const float4*)(r1 + c4);
        v1 = *(const float4*)(r1 + 128 + c4);
    }

    float ax = 0.f, ay = 0.f, az = 0.f, aw = 0.f, den = 0.f;
    for (int j = 0; j < c; j++) {
        const float4 k4 = k0, v4 = v0;
        k0 = k1; v0 = v1;
        if (j + 2 < c) {
            const float* rn = KV + (size_t)__ldg(srt + st + j + 2) * 256;
            k1 = *(const float4*)(rn + c4);
            v1 = *(const float4*)(rn + 128 + c4);
        }
        float p = q4.x * k4.x + q4.y * k4.y + q4.z * k4.z + q4.w * k4.w;
        p += __shfl_xor_sync(0xffffffffu, p, 1);
        p += __shfl_xor_sync(0xffffffffu, p, 2);
        p += __shfl_xor_sync(0xffffffffu, p, 4);
        const float w = __expf(p);
        den += w;
        ax += w * v4.x; ay += w * v4.y; az += w * v4.z; aw += w * v4.w;
    }
    const float inv = 1.f / den;
    __stcs((float4*)zp, make_float4(fmaxf(ax * inv, 0.f), fmaxf(ay * inv, 0.f),
                                    fmaxf(az * inv, 0.f), fmaxf(aw * inv, 0.f)));
}

extern "C" void kernel_launch(void* const* d_in, const int* in_sizes, int n_in,
                              void* d_out, int out_size)
{
    const float* h_user    = (const float*)d_in[0];
    const float* h_item    = (const float*)d_in[1];
    const int*   edge_user = (const int*)d_in[2];
    const int*   edge_item = (const int*)d_in[3];
    const float* u_wq = (const float*)d_in[4];
    const float* u_wk = (const float*)d_in[5];
    const float* u_wv = (const float*)d_in[6];
    const float* i_wq = (const float*)d_in[7];
    const float* i_wk = (const float*)d_in[8];
    const float* i_wv = (const float*)d_in[9];
    float* out = (float*)d_out;

    const int nE = in_sizes[2];
    const int Mu = in_sizes[0] / DIN;
    const int Mi = in_sizes[1] / DIN;

    float *Qu, *Qi, *KVu, *KVi;
    int *cnt, *srt;
    __nv_bfloat16* WB;
    cudaGetSymbolAddress((void**)&Qu, g_Qu);
    cudaGetSymbolAddress((void**)&Qi, g_Qi);
    cudaGetSymbolAddress((void**)&KVu, g_KVu);
    cudaGetSymbolAddress((void**)&KVi, g_KVi);
    cudaGetSymbolAddress((void**)&cnt, g_cnt);
    cudaGetSymbolAddress((void**)&srt, g_srt);
    cudaGetSymbolAddress((void**)&WB, g_WB);

    cudaFuncSetAttribute(proj_wmma, cudaFuncAttributeMaxDynamicSharedMemorySize, SMEM_PROJ);

    // ---- memset cnt + split_w (tiny) ----
    cudaMemsetAsync(cnt, 0, sizeof(int) * NSEG);
    split_w_kernel<<<384, 256>>>(u_wq, u_wk, u_wv, i_wq, i_wk, i_wv, WB);

    // ---- projections + hidden bucket scatter (one merged launch) ----
    const int tilesU = (Mu + 63) / 64, tilesI = (Mi + 63) / 64;
    const int tilesT = tilesU + tilesI;
    const int chunkE = (2 * nE + tilesT - 1) / tilesT;
    proj_wmma<<<tilesT, 128, SMEM_PROJ>>>(h_user, h_item, WB,
                                          Qu, Qi, KVu, KVi, Mu, Mi, tilesU,
                                          edge_user, edge_item, cnt, srt, nE, chunkE);

    // ---- fused attention gather + softmax-normalize + relu ----
    gather_kernel<<<(NSEG + 1) / 2, 64>>>(Qu, Qi, KVu, KVi, cnt, srt, out);
}

// round 17
// speedup vs baseline: 1.2079x; 1.0502x over previous
#include <cuda_runtime.h>
#include <cuda_bf16.h>
#include <mma.h>
#include <cstdint>

using namespace nvcuda;

#define NUSER 100000
#define NITEM 50000
#define NSEG  150000            // NUSER + NITEM
#define NEDGE 400000
#define DIN 128
#define BCAP 64                 // per-destination bucket capacity (max degree ~30)

// Scratch (allocation-free rule: __device__ globals)
// Q separate [node][128]; K,V interleaved per node: [node][0:128)=K, [128:256)=V
__device__ float g_Qu[(size_t)NUSER * DIN];
__device__ float g_Qi[(size_t)NITEM * DIN];
__device__ float g_KVu[(size_t)NUSER * 256];
__device__ float g_KVi[(size_t)NITEM * 256];
__device__ int g_cnt[NSEG];
__device__ int g_srt[(size_t)NSEG * BCAP];
// pre-split weights: 6 matrices x {hi,lo} planes, logical [k][n] (n = h*32+e)
__device__ __nv_bfloat16 g_WB[6 * 2 * 128 * 128];

// ---------------- cp.async helpers (baseline sm_80 PTX) ---------------------
__device__ __forceinline__ void cp_async16(void* smem_dst, const void* gsrc) {
    const uint32_t s = (uint32_t)__cvta_generic_to_shared(smem_dst);
    asm volatile("cp.async.cg.shared.global [%0], [%1], 16;" :: "r"(s), "l"(gsrc));
}
#define CP_COMMIT() asm volatile("cp.async.commit_group;" ::: "memory")
#define CP_WAIT0()  asm volatile("cp.async.wait_group 0;" ::: "memory")

// ---------------- W pre-split: fp32 [h][k][e] -> bf16 hi/lo [k][n] ----------
__global__ __launch_bounds__(256) void split_w_kernel(
    const float* __restrict__ w0, const float* __restrict__ w1, const float* __restrict__ w2,
    const float* __restrict__ w3, const float* __restrict__ w4, const float* __restrict__ w5,
    __nv_bfloat16* __restrict__ WB)
{
    const int bx = blockIdx.x;                       // 384 blocks = 6 * 64
    const int m = bx >> 6;
    const float* w = m == 0 ? w0 : m == 1 ? w1 : m == 2 ? w2 : m == 3 ? w3 : m == 4 ? w4 : w5;
    __nv_bfloat16* hi = WB + (size_t)m * 2 * 16384;
    __nv_bfloat16* lo = hi + 16384;
    const int i = (bx & 63) * 256 + threadIdx.x;
    const int k = i >> 7, n = i & 127;
    const float v = w[(n >> 5) * 4096 + k * 32 + (n & 31)];
    const __nv_bfloat16 h = __float2bfloat16(v);
    hi[i] = h;
    lo[i] = __float2bfloat16(v - __bfloat162float(h));
}

// ============ projection GEMM (merged user+item) + hidden bucket scatter ====
// Y[M,128] = X[M,128] @ Wlogical[128,128], bf16 wmma 3-term split emulation.
// 128 threads = 4 warps in 2x2, warp tile 32x64. B staged in 32-k-row chunks
// (hi+lo, 17.4KB) via cp.async double buffering — 12 phases; total smem
// 69.6KB -> 3 CTAs/SM (12 warps/SM) for cross-CTA phase overlap.
// Bucket scatter slice hidden after X staging. Q stride 128; K/V interleaved
// stride 256. M % 16 == 0 holds.

static constexpr int LDA = 136;   // bf16 elems (272B rows)
static constexpr int LDB = 136;
static constexpr int BROWS = 32;  // k-rows per B chunk
static constexpr int A_BYTES    = 2 * 64 * LDA * 2;        // 34816
static constexpr int BBUF_BYTES = 2 * BROWS * LDB * 2;     // 17408 (hi 32 + lo 32 rows)
static constexpr int SMEM_PROJ  = A_BYTES + 2 * BBUF_BYTES; // 69632 B -> 3 CTAs/SM

// stream one 32-row B chunk (phase = mSel*4 + c) into bufBase via cp.async
__device__ __forceinline__ void issue_b_chunk(
    const __nv_bfloat16* WBs, int phase, char* bufBase, int tid)
{
    const int mSel = phase >> 2, c = phase & 3;
    const __nv_bfloat16* Wm = WBs + (size_t)mSel * 2 * 16384;
    const char* srcHi = (const char*)(Wm + c * 4096);            // 8KB contiguous
    const char* srcLo = (const char*)(Wm + 16384 + c * 4096);
    #pragma unroll
    for (int i = tid; i < 1024; i += 128) {
        const int plane = i >> 9;             // 0 = hi, 1 = lo
        const int idx = i & 511;              // uint4 index within plane chunk
        const int r = idx >> 4, c16 = idx & 15;   // 32 rows x 16 uint4/row
        char* dst = bufBase + plane * (BROWS * LDB * 2) + r * (LDB * 2) + c16 * 16;
        const char* s = (plane ? srcLo : srcHi) + (size_t)idx * 16;
        cp_async16(dst, s);
    }
}

__global__ __launch_bounds__(128, 3) void proj_wmma(
    const float* __restrict__ Xu, const float* __restrict__ Xi,
    const __nv_bfloat16* __restrict__ WB,
    float* __restrict__ Qu, float* __restrict__ Qi,
    float* __restrict__ KVu, float* __restrict__ KVi,
    int Mu, int Mi, int tilesU,
    const int* __restrict__ eu, const int* __restrict__ ei,
    int* __restrict__ cnt, int* __restrict__ srt, int nE, int chunkE)
{
    extern __shared__ char smraw[];
    __nv_bfloat16* Ah = (__nv_bfloat16*)smraw;          // 64 x LDA
    __nv_bfloat16* Al = Ah + 64 * LDA;
    char* bBuf[2] = { smraw + A_BYTES, smraw + A_BYTES + BBUF_BYTES };

    const int tid  = threadIdx.x;
    const int wid  = tid >> 5;
    const int lane = tid & 31;

    const bool isU = (int)blockIdx.x < tilesU;
    const int tile0 = (isU ? blockIdx.x : blockIdx.x - tilesU) * 64;
    const int M = isU ? Mu : Mi;
    const float* X = isU ? Xu : Xi;
    const __nv_bfloat16* WBs = WB + (isU ? 0 : (size_t)3 * 2 * 16384);
    float* Qp  = isU ? Qu  : Qi;
    float* KVp = isU ? KVu : KVi;

    // ---- kick off B chunk 0 immediately (overlaps X staging) ----
    issue_b_chunk(WBs, 0, bBuf[0], tid);
    CP_COMMIT();

    // ---- stage X tile ONCE -> Ah/Al (warp per row, float4 per lane) ----
    #pragma unroll
    for (int r0 = 0; r0 < 64; r0 += 4) {
        const int row = r0 + wid;
        const int grow = tile0 + row;
        float4 av = make_float4(0.f, 0.f, 0.f, 0.f);
        if (grow < M) av = *(const float4*)(X + (size_t)grow * 128 + lane * 4);
        const float vs[4] = {av.x, av.y, av.z, av.w};
        __nv_bfloat16 hb[4], lb[4];
        #pragma unroll
        for (int j = 0; j < 4; j++) {
            hb[j] = __float2bfloat16(vs[j]);
            lb[j] = __float2bfloat16(vs[j] - __bfloat162float(hb[j]));
        }
        *(uint2*)&Ah[row * LDA + lane * 4] = *(const uint2*)hb;
        *(uint2*)&Al[row * LDA + lane * 4] = *(const uint2*)lb;
    }

    // ---- hidden bucket scatter: slice of edges, overlaps cp.async latency --
    {
        const int base = blockIdx.x * chunkE;
        const int end  = min(base + chunkE, 2 * nE);
        for (int t = base + tid; t < end; t += 128) {
            if (t < nE) {
                const int d = eu[t];
                const int p = atomicAdd(&cnt[d], 1);
                if (p < BCAP) srt[(size_t)d * BCAP + p] = ei[t];
            } else {
                const int e = t - nE;
                const int d = NUSER + ei[e];
                const int p = atomicAdd(&cnt[d], 1);
                if (p < BCAP) srt[(size_t)d * BCAP + p] = eu[e];
            }
        }
    }

    const int wr = wid >> 1;          // warp row (32 rows)
    const int wc = wid & 1;           // warp col (64 cols)
    int pb = 0;                        // current B buffer

    for (int mSel = 0; mSel < 3; mSel++) {
        wmma::fragment<wmma::accumulator, 16, 16, 16, float> c[2][4];
        #pragma unroll
        for (int i = 0; i < 2; i++)
            #pragma unroll
            for (int j = 0; j < 4; j++) wmma::fill_fragment(c[i][j], 0.f);

        #pragma unroll
        for (int ch = 0; ch < 4; ch++) {
            const int phase = mSel * 4 + ch;
            CP_WAIT0();          // our chunk `phase` is in
            __syncthreads();     // all threads' chunk in; all done reading other buf
            if (phase + 1 < 12) {
                issue_b_chunk(WBs, phase + 1, bBuf[pb ^ 1], tid);
                CP_COMMIT();
            }
            const __nv_bfloat16* BhB = (const __nv_bfloat16*)bBuf[pb];
            const __nv_bfloat16* BlB = BhB + BROWS * LDB;
            const int kBase = ch * BROWS;

            #pragma unroll
            for (int kk = 0; kk < BROWS; kk += 16) {
                wmma::fragment<wmma::matrix_a, 16, 16, 16, __nv_bfloat16, wmma::row_major> ah[2], al[2];
                #pragma unroll
                for (int i = 0; i < 2; i++) {
                    wmma::load_matrix_sync(ah[i], Ah + (wr * 32 + i * 16) * LDA + kBase + kk, LDA);
                    wmma::load_matrix_sync(al[i], Al + (wr * 32 + i * 16) * LDA + kBase + kk, LDA);
                }
                #pragma unroll
                for (int j = 0; j < 4; j++) {
                    wmma::fragment<wmma::matrix_b, 16, 16, 16, __nv_bfloat16, wmma::row_major> bh, bl;
                    wmma::load_matrix_sync(bh, BhB + kk * LDB + wc * 64 + j * 16, LDB);
                    wmma::load_matrix_sync(bl, BlB + kk * LDB + wc * 64 + j * 16, LDB);
                    #pragma unroll
                    for (int i = 0; i < 2; i++) {
                        wmma::mma_sync(c[i][j], ah[i], bh, c[i][j]);
                        wmma::mma_sync(c[i][j], al[i], bh, c[i][j]);
                        wmma::mma_sync(c[i][j], ah[i], bl, c[i][j]);
                    }
                }
            }
            pb ^= 1;
        }

        // ---- epilogue: direct global stores (M % 16 == 0) ----
        float* Y = (mSel == 0) ? Qp : KVp;
        const int ldY  = (mSel == 0) ? 128 : 256;
        const int coff = (mSel == 2) ? 128 : 0;
        #pragma unroll
        for (int i = 0; i < 2; i++) {
            const int grow = tile0 + wr * 32 + i * 16;
            if (grow + 16 <= M) {
                #pragma unroll
                for (int j = 0; j < 4; j++)
                    wmma::store_matrix_sync(Y + (size_t)grow * ldY + coff + wc * 64 + j * 16,
                                            c[i][j], ldY, wmma::mem_row_major);
            }
        }
    }
}

// ============== gather: one warp per destination, fused finalize ============
// 64-thread CTAs (2 warps): straggler warp holds only 1 sibling. Q read
// streaming (__ldcs), output streaming (__stcs) to keep KV resident in L2.
__global__ __launch_bounds__(64, 16) void gather_kernel(
    const float* __restrict__ Qu, const float* __restrict__ Qi,
    const float* __restrict__ KVu, const float* __restrict__ KVi,
    const int* __restrict__ cnt, const int* __restrict__ srt,
    float* __restrict__ out)
{
    const int g = blockIdx.x * 2 + (threadIdx.x >> 5);
    if (g >= NSEG) return;
    const int lane = threadIdx.x & 31;
    const int c4 = (lane & 7) * 4 + (lane >> 3) * 32;   // this lane's 4 dims

    float* zp = out + (size_t)g * 128 + c4;
    const int c = min(cnt[g], BCAP);
    if (c == 0) {
        __stcs((float4*)zp, make_float4(0.f, 0.f, 0.f, 0.f));
        return;
    }

    const float* Q;
    const float* KV;
    int qrow;
    if (g < NUSER) { Q = Qu; KV = KVi; qrow = g; }
    else           { Q = Qi; KV = KVu; qrow = g - NUSER; }

    const float4 q4 = __ldcs((const float4*)(Q + (size_t)qrow * 128 + c4));
    const int st = g * BCAP;

    // depth-2 prefetch pipeline over 1KB KV records
    float4 k0, v0, k1, v1;
    {
        const float* r0 = KV + (size_t)__ldg(srt + st) * 256;
        k0 = *(const float4*)(r0 + c4);
        v0 = *(const float4*)(r0 + 128 + c4);
    }
    if (c > 1) {
        const float* r1 = KV + (size_t)__ldg(srt + st + 1) * 256;
        k1 = *(const float4*)(r1 + c4);
        v1 = *(const float4*)(r1 + 128 + c4);
    }

    float ax = 0.f, ay = 0.f, az = 0.f, aw = 0.f, den = 0.f;
    for (int j = 0; j < c; j++) {
        const float4 k4 = k0, v4 = v0;
        k0 = k1; v0 = v1;
        if (j + 2 < c) {
            const float* rn = KV + (size_t)__ldg(srt + st + j + 2) * 256;
            k1 = *(const float4*)(rn + c4);
            v1 = *(const float4*)(rn + 128 + c4);
        }
        float p = q4.x * k4.x + q4.y * k4.y + q4.z * k4.z + q4.w * k4.w;
        p += __shfl_xor_sync(0xffffffffu, p, 1);
        p += __shfl_xor_sync(0xffffffffu, p, 2);
        p += __shfl_xor_sync(0xffffffffu, p, 4);
        const float w = __expf(p);
        den += w;
        ax += w * v4.x; ay += w * v4.y; az += w * v4.z; aw += w * v4.w;
    }
    const float inv = 1.f / den;
    __stcs((float4*)zp, make_float4(fmaxf(ax * inv, 0.f), fmaxf(ay * inv, 0.f),
                                    fmaxf(az * inv, 0.f), fmaxf(aw * inv, 0.f)));
}

extern "C" void kernel_launch(void* const* d_in, const int* in_sizes, int n_in,
                              void* d_out, int out_size)
{
    const float* h_user    = (const float*)d_in[0];
    const float* h_item    = (const float*)d_in[1];
    const int*   edge_user = (const int*)d_in[2];
    const int*   edge_item = (const int*)d_in[3];
    const float* u_wq = (const float*)d_in[4];
    const float* u_wk = (const float*)d_in[5];
    const float* u_wv = (const float*)d_in[6];
    const float* i_wq = (const float*)d_in[7];
    const float* i_wk = (const float*)d_in[8];
    const float* i_wv = (const float*)d_in[9];
    float* out = (float*)d_out;

    const int nE = in_sizes[2];
    const int Mu = in_sizes[0] / DIN;
    const int Mi = in_sizes[1] / DIN;

    float *Qu, *Qi, *KVu, *KVi;
    int *cnt, *srt;
    __nv_bfloat16* WB;
    cudaGetSymbolAddress((void**)&Qu, g_Qu);
    cudaGetSymbolAddress((void**)&Qi, g_Qi);
    cudaGetSymbolAddress((void**)&KVu, g_KVu);
    cudaGetSymbolAddress((void**)&KVi, g_KVi);
    cudaGetSymbolAddress((void**)&cnt, g_cnt);
    cudaGetSymbolAddress((void**)&srt, g_srt);
    cudaGetSymbolAddress((void**)&WB, g_WB);

    cudaFuncSetAttribute(proj_wmma, cudaFuncAttributeMaxDynamicSharedMemorySize, SMEM_PROJ);

    // ---- memset cnt + split_w (tiny) ----
    cudaMemsetAsync(cnt, 0, sizeof(int) * NSEG);
    split_w_kernel<<<384, 256>>>(u_wq, u_wk, u_wv, i_wq, i_wk, i_wv, WB);

    // ---- projections + hidden bucket scatter (one merged launch) ----
    const int tilesU = (Mu + 63) / 64, tilesI = (Mi + 63) / 64;
    const int tilesT = tilesU + tilesI;
    const int chunkE = (2 * nE + tilesT - 1) / tilesT;
    proj_wmma<<<tilesT, 128, SMEM_PROJ>>>(h_user, h_item, WB,
                                          Qu, Qi, KVu, KVi, Mu, Mi, tilesU,
                                          edge_user, edge_item, cnt, srt, nE, chunkE);

    // ---- fused attention gather + softmax-normalize + relu ----
    gather_kernel<<<(NSEG + 1) / 2, 64>>>(Qu, Qi, KVu, KVi, cnt, srt, out);
}